// round 12
// baseline (speedup 1.0000x reference)
#include <cuda_runtime.h>
#include <cuda_bf16.h>
#include <cuda_fp16.h>
#include <math.h>
#include <stdint.h>

#define TT 2048
#define HID 4608
#define NH 36
#define NKV 4
#define HD 128
#define QKVD 5632
#define GROUP 9
#define ATT_SCALE 0.08838834764831843f
#define LOG2E 1.4426950408889634f

// ---------------- scratch ----------------
__device__ float g_qkv[TT * QKVD];
__device__ __half g_hid_hi[TT * HID];
__device__ __half g_hid_lo[TT * HID];
__device__ __half g_wqkv_h[QKVD * HID];
__device__ __half g_wo_h[HID * HID];
__device__ __half g_attn_hi[TT * HID];
__device__ __half g_attn_lo[TT * HID];

__device__ __forceinline__ uint32_t smem_u32(const void* p) {
    uint32_t a;
    asm("{ .reg .u64 t; cvta.to.shared.u64 t, %1; cvt.u32.u64 %0, t; }" : "=r"(a) : "l"(p));
    return a;
}
__device__ __forceinline__ void ldm_x4(uint32_t* r, uint32_t addr) {
    asm volatile("ldmatrix.sync.aligned.m8n8.x4.shared.b16 {%0,%1,%2,%3}, [%4];"
                 : "=r"(r[0]), "=r"(r[1]), "=r"(r[2]), "=r"(r[3]) : "r"(addr));
}
__device__ __forceinline__ void ldm_x4_t(uint32_t* r, uint32_t addr) {
    asm volatile("ldmatrix.sync.aligned.m8n8.x4.trans.shared.b16 {%0,%1,%2,%3}, [%4];"
                 : "=r"(r[0]), "=r"(r[1]), "=r"(r[2]), "=r"(r[3]) : "r"(addr));
}
// bf16 MMA, f32 acc (attention)
__device__ __forceinline__ void mma16816(float* d, const uint32_t* a, uint32_t b0, uint32_t b1) {
    asm volatile(
        "mma.sync.aligned.m16n8k16.row.col.f32.bf16.bf16.f32 "
        "{%0,%1,%2,%3}, {%4,%5,%6,%7}, {%8,%9}, {%0,%1,%2,%3};"
        : "+f"(d[0]), "+f"(d[1]), "+f"(d[2]), "+f"(d[3])
        : "r"(a[0]), "r"(a[1]), "r"(a[2]), "r"(a[3]), "r"(b0), "r"(b1));
}
// fp16 MMA, f32 acc (GEMM hi term)
__device__ __forceinline__ void mma16816h(float* d, const uint32_t* a, uint32_t b0, uint32_t b1) {
    asm volatile(
        "mma.sync.aligned.m16n8k16.row.col.f32.f16.f16.f32 "
        "{%0,%1,%2,%3}, {%4,%5,%6,%7}, {%8,%9}, {%0,%1,%2,%3};"
        : "+f"(d[0]), "+f"(d[1]), "+f"(d[2]), "+f"(d[3])
        : "r"(a[0]), "r"(a[1]), "r"(a[2]), "r"(a[3]), "r"(b0), "r"(b1));
}
// fp16 MMA, f16 acc (GEMM lo term — magnitudes ~2^-11 of total; f16 acc safe,
// verified rel_err 5.27e-4 in round 11)
__device__ __forceinline__ void mma16816hh(uint32_t* d, const uint32_t* a, uint32_t b0, uint32_t b1) {
    asm volatile(
        "mma.sync.aligned.m16n8k16.row.col.f16.f16.f16.f16 "
        "{%0,%1}, {%2,%3,%4,%5}, {%6,%7}, {%0,%1};"
        : "+r"(d[0]), "+r"(d[1])
        : "r"(a[0]), "r"(a[1]), "r"(a[2]), "r"(a[3]), "r"(b0), "r"(b1));
}
__device__ __forceinline__ uint32_t pack2(__nv_bfloat16 a, __nv_bfloat16 b) {
    __nv_bfloat162 t(a, b);
    return *reinterpret_cast<uint32_t*>(&t);
}
__device__ __forceinline__ uint32_t pack2h(__half a, __half b) {
    __half2 t(a, b);
    return *reinterpret_cast<uint32_t*>(&t);
}
__device__ __forceinline__ void split4(float4 v, uint2& hi, uint2& lo) {
    __nv_bfloat16 h0 = __float2bfloat16(v.x), h1 = __float2bfloat16(v.y);
    __nv_bfloat16 h2 = __float2bfloat16(v.z), h3 = __float2bfloat16(v.w);
    __nv_bfloat16 l0 = __float2bfloat16(v.x - __bfloat162float(h0));
    __nv_bfloat16 l1 = __float2bfloat16(v.y - __bfloat162float(h1));
    __nv_bfloat16 l2 = __float2bfloat16(v.z - __bfloat162float(h2));
    __nv_bfloat16 l3 = __float2bfloat16(v.w - __bfloat162float(h3));
    hi.x = pack2(h0, h1); hi.y = pack2(h2, h3);
    lo.x = pack2(l0, l1); lo.y = pack2(l2, l3);
}
__device__ __forceinline__ void split4h(float4 v, uint2& hi, uint2& lo) {
    __half h0 = __float2half(v.x), h1 = __float2half(v.y);
    __half h2 = __float2half(v.z), h3 = __float2half(v.w);
    __half l0 = __float2half(v.x - __half2float(h0));
    __half l1 = __float2half(v.y - __half2float(h1));
    __half l2 = __float2half(v.z - __half2float(h2));
    __half l3 = __float2half(v.w - __half2float(h3));
    hi.x = pack2h(h0, h1); hi.y = pack2h(h2, h3);
    lo.x = pack2h(l0, l1); lo.y = pack2h(l2, l3);
}

// ---------------------------------------------------------------------------
// fp32 -> fp16 hi/lo split (activations)
// ---------------------------------------------------------------------------
__global__ __launch_bounds__(256) void split_f16(const float* __restrict__ x,
                                                 __half* __restrict__ hi,
                                                 __half* __restrict__ lo,
                                                 int n4)
{
    int i = blockIdx.x * 256 + threadIdx.x;
    if (i >= n4) return;
    float4 v = ((const float4*)x)[i];
    uint2 H, L;
    split4h(v, H, L);
    ((uint2*)hi)[i] = H;
    ((uint2*)lo)[i] = L;
}

// fp32 -> fp16 plain convert (weights)
__global__ __launch_bounds__(256) void conv_f16(const float* __restrict__ x,
                                                __half* __restrict__ y,
                                                int n4)
{
    int i = blockIdx.x * 256 + threadIdx.x;
    if (i >= n4) return;
    float4 v = ((const float4*)x)[i];
    uint2 H;
    H.x = pack2h(__float2half(v.x), __float2half(v.y));
    H.y = pack2h(__float2half(v.z), __float2half(v.w));
    ((uint2*)y)[i] = H;
}

// ---------------------------------------------------------------------------
// fp16x2 GEMM: C = A @ B^T + bias. A hi/lo fp16, B fp16.
// BK=64, 3-stage pipeline (round-10 proven structure).
// Lo term on f16 accumulator (isolated change this round).
// ---------------------------------------------------------------------------
#define GBM 128
#define GBN 128
#define GBK 64
#define ROWB 144
#define TILE_B (128 * ROWB)         // 18432
#define STAGE_B (3 * TILE_B)        // Ahi, Alo, Bh = 55296
#define NSTG 3
#define GEMM_SMEM (NSTG * STAGE_B)  // 165888

__global__ __launch_bounds__(512, 1) void gemm_f16(
    const __half* __restrict__ Ahi, const __half* __restrict__ Alo,
    const __half* __restrict__ Bh,
    const float* __restrict__ bias, float* __restrict__ C,
    int M, int N, int K)
{
    extern __shared__ char smem[];
    const uint32_t sb = smem_u32(smem);
    const int tid = threadIdx.x, wid = tid >> 5, lane = tid & 31;
    const int warp_m = wid & 3;
    const int warp_n = wid >> 2;
    const int bm = blockIdx.x * GBM, bn = blockIdx.y * GBN;

    float acc[2][4][4];
    uint32_t accl[2][4][2];
#pragma unroll
    for (int i = 0; i < 2; i++)
#pragma unroll
        for (int j = 0; j < 4; j++) {
#pragma unroll
            for (int q = 0; q < 4; q++) acc[i][j][q] = 0.0f;
            accl[i][j][0] = 0u; accl[i][j][1] = 0u;
        }

    // stage loader: 3 tiles x 128 rows x 8 chunks(16B) = 3072 chunks, 6/thread
    auto load_stage = [&](int stg, int k0) {
        uint32_t base = sb + stg * STAGE_B;
#pragma unroll
        for (int i = 0; i < 6; i++) {
            int c = tid + i * 512;
            int tile = c >> 10;         // 0:Ahi 1:Alo 2:Bh
            int idx = c & 1023;
            int row = idx >> 3, ch = idx & 7;
            const __half* g;
            int grow;
            if (tile == 0) { g = Ahi; grow = bm + row; }
            else if (tile == 1) { g = Alo; grow = bm + row; }
            else { g = Bh; grow = bn + row; }
            const char* src = (const char*)(g + (size_t)grow * K + k0) + ch * 16;
            uint32_t dst = base + tile * TILE_B + row * ROWB + ch * 16;
            asm volatile("cp.async.cg.shared.global [%0], [%1], 16;" :: "r"(dst), "l"(src));
        }
        asm volatile("cp.async.commit_group;" ::: "memory");
    };

    const int NKB = K / GBK;   // 72
    load_stage(0, 0);
    load_stage(1, GBK);

    const int a_row = (lane & 15);
    const int a_kh = lane >> 4;
    const int b_nrow = (lane & 7) + ((lane >> 4) & 1) * 8;
    const int b_kh = (lane >> 3) & 1;

    for (int kb = 0; kb < NKB; kb++) {
        const int cur = kb % NSTG;
        if (kb + 1 < NKB) { asm volatile("cp.async.wait_group 1;" ::: "memory"); }
        else              { asm volatile("cp.async.wait_group 0;" ::: "memory"); }
        __syncthreads();

        if (kb + 2 < NKB) load_stage((kb + 2) % NSTG, (kb + 2) * GBK);

        const uint32_t stage = sb + cur * STAGE_B;
        const uint32_t Ah = stage;
        const uint32_t Al = stage + TILE_B;
        const uint32_t Bt = stage + 2 * TILE_B;

#pragma unroll
        for (int ks = 0; ks < 4; ks++) {
            uint32_t ah[2][4], al[2][4];
#pragma unroll
            for (int mf = 0; mf < 2; mf++) {
                uint32_t off = (warp_m * 32 + mf * 16 + a_row) * ROWB + ks * 32 + a_kh * 16;
                ldm_x4(ah[mf], Ah + off);
                ldm_x4(al[mf], Al + off);
            }
            uint32_t bh[2][4];
#pragma unroll
            for (int p = 0; p < 2; p++) {
                uint32_t off = (warp_n * 32 + p * 16 + b_nrow) * ROWB + ks * 32 + b_kh * 16;
                ldm_x4(bh[p], Bt + off);
            }
#pragma unroll
            for (int mf = 0; mf < 2; mf++)
#pragma unroll
                for (int nf = 0; nf < 4; nf++) {
                    const int p = nf >> 1, o = (nf & 1) * 2;
                    mma16816h(acc[mf][nf], ah[mf], bh[p][o], bh[p][o + 1]);   // Ah*B, f32 acc
                }
#pragma unroll
            for (int mf = 0; mf < 2; mf++)
#pragma unroll
                for (int nf = 0; nf < 4; nf++) {
                    const int p = nf >> 1, o = (nf & 1) * 2;
                    mma16816hh(accl[mf][nf], al[mf], bh[p][o], bh[p][o + 1]); // Al*B, f16 acc
                }
        }
    }

    const int qr = lane >> 2, qc = (lane & 3) * 2;
#pragma unroll
    for (int mf = 0; mf < 2; mf++) {
        int row0 = bm + warp_m * 32 + mf * 16 + qr;
#pragma unroll
        for (int nf = 0; nf < 4; nf++) {
            int col = bn + warp_n * 32 + nf * 8 + qc;
            float2 bv = *(const float2*)(bias + col);
            __half2 lo01 = *reinterpret_cast<__half2*>(&accl[mf][nf][0]);
            __half2 lo23 = *reinterpret_cast<__half2*>(&accl[mf][nf][1]);
            float2 v0 = { acc[mf][nf][0] + __low2float(lo01) + bv.x,
                          acc[mf][nf][1] + __high2float(lo01) + bv.y };
            float2 v1 = { acc[mf][nf][2] + __low2float(lo23) + bv.x,
                          acc[mf][nf][3] + __high2float(lo23) + bv.y };
            *(float2*)(C + (size_t)row0 * N + col) = v0;
            *(float2*)(C + (size_t)(row0 + 8) * N + col) = v1;
        }
    }
}

// ---------------------------------------------------------------------------
// NeoX RoPE (4 heads per 256-thread block)
// ---------------------------------------------------------------------------
__global__ __launch_bounds__(256) void rope_kernel(float* __restrict__ qkv,
                                                   const int* __restrict__ positions)
{
    const int tid = threadIdx.x;
    const int d = tid & 63;
    const int hh = blockIdx.x * 4 + (tid >> 6);
    const int t = blockIdx.y;

    float* base;
    if (hh < NH) base = qkv + (size_t)t * QKVD + hh * HD;
    else         base = qkv + (size_t)t * QKVD + NH * HD + (hh - NH) * HD;

    const float pos = (float)positions[t];
    const float inv_freq = expf(-11.512925464970229f * ((float)d / 64.0f));
    const float ang = pos * inv_freq;
    float s, c;
    sincosf(ang, &s, &c);

    const float x1 = base[d];
    const float x2 = base[d + 64];
    base[d]      = x1 * c - x2 * s;
    base[d + 64] = x2 * c + x1 * s;
}

// ---------------------------------------------------------------------------
// Windowed causal flash attention on HMMA (bf16x3 internally).
// Epilogue writes fp16 hi/lo for the fp16x2 output GEMM.
// ---------------------------------------------------------------------------
#define AROWB 272
#define AQ_B (128 * AROWB)
#define AK_B (64 * AROWB)
#define ATTN_SMEM (AQ_B * 2 + AK_B * 4)

__global__ __launch_bounds__(256, 1) void attn_mma(
    const float* __restrict__ qkv,
    __half* __restrict__ outHi,
    __half* __restrict__ outLo,
    const int* __restrict__ winp)
{
    extern __shared__ char smem[];
    const uint32_t sb = smem_u32(smem);
    const uint32_t Qhi = sb,                Qlo = sb + AQ_B;
    const uint32_t Khi = sb + 2 * AQ_B,     Klo = Khi + AK_B;
    const uint32_t Vhi = Klo + AK_B,        Vlo = Vhi + AK_B;

    const int tid = threadIdx.x, w = tid >> 5, lane = tid & 31;
    const int h = blockIdx.y, qt0 = blockIdx.x * 128;
    const int kvh = h / GROUP;
    const int window = *winp;
    const int g = lane >> 2, qc2 = (lane & 3) * 2;

    const size_t qOff = (size_t)h * HD;
    const size_t kOff = (size_t)NH * HD + (size_t)kvh * HD;
    const size_t vOff = kOff + (size_t)NKV * HD;

    for (int idx = tid; idx < 128 * 32; idx += 256) {
        int row = idx >> 5, c4 = idx & 31;
        float4 v = *(const float4*)(qkv + (size_t)(qt0 + row) * QKVD + qOff + c4 * 4);
        uint2 H, L;
        split4(v, H, L);
        *(uint2*)(smem + (Qhi - sb) + row * AROWB + c4 * 8) = H;
        *(uint2*)(smem + (Qlo - sb) + row * AROWB + c4 * 8) = L;
    }

    float m0 = -1e30f, m1 = -1e30f, l0 = 0.0f, l1 = 0.0f;
    float O[16][4];
#pragma unroll
    for (int i = 0; i < 16; i++)
#pragma unroll
        for (int j = 0; j < 4; j++) O[i][j] = 0.0f;

    const int a_row = (lane & 15);
    const int a_kh = lane >> 4;
    const int b_nrow = (lane & 7) + ((lane >> 4) & 1) * 8;
    const int b_kh = (lane >> 3) & 1;
    const int vkr = (lane & 7) + ((lane >> 3) & 1) * 8;
    const int vnc = ((lane >> 4) & 1) * 8;

    const float sc = ATT_SCALE * LOG2E;
    const int qrow0 = qt0 + w * 16 + g;
    const int qrow1 = qrow0 + 8;

    int sBegin = qt0 - window + 1;
    if (sBegin < 0) sBegin = 0;
    sBegin &= ~63;
    const int sEnd = qt0 + 127;

    for (int s0 = sBegin; s0 <= sEnd; s0 += 64) {
        __syncthreads();
        for (int idx = tid; idx < 64 * 32; idx += 256) {
            int row = idx >> 5, c4 = idx & 31;
            float4 kv = *(const float4*)(qkv + (size_t)(s0 + row) * QKVD + kOff + c4 * 4);
            uint2 H, L;
            split4(kv, H, L);
            *(uint2*)(smem + (Khi - sb) + row * AROWB + c4 * 8) = H;
            *(uint2*)(smem + (Klo - sb) + row * AROWB + c4 * 8) = L;
            float4 vv = *(const float4*)(qkv + (size_t)(s0 + row) * QKVD + vOff + c4 * 4);
            split4(vv, H, L);
            *(uint2*)(smem + (Vhi - sb) + row * AROWB + c4 * 8) = H;
            *(uint2*)(smem + (Vlo - sb) + row * AROWB + c4 * 8) = L;
        }
        __syncthreads();

        float S[8][4];
#pragma unroll
        for (int i = 0; i < 8; i++)
#pragma unroll
            for (int j = 0; j < 4; j++) S[i][j] = 0.0f;

#pragma unroll
        for (int kf = 0; kf < 8; kf++) {
            uint32_t ah[4], al[4];
            uint32_t aoff = (w * 16 + a_row) * AROWB + kf * 32 + a_kh * 16;
            ldm_x4(ah, Qhi + aoff);
            ldm_x4(al, Qlo + aoff);
#pragma unroll
            for (int nt = 0; nt < 4; nt++) {
                uint32_t bh[4], bl[4];
                uint32_t boff = (nt * 16 + b_nrow) * AROWB + kf * 32 + b_kh * 16;
                ldm_x4(bh, Khi + boff);
                ldm_x4(bl, Klo + boff);
                mma16816(S[2 * nt],     ah, bh[0], bh[1]);
                mma16816(S[2 * nt + 1], ah, bh[2], bh[3]);
                mma16816(S[2 * nt],     ah, bl[0], bl[1]);
                mma16816(S[2 * nt + 1], ah, bl[2], bl[3]);
                mma16816(S[2 * nt],     al, bh[0], bh[1]);
                mma16816(S[2 * nt + 1], al, bh[2], bh[3]);
            }
        }

#pragma unroll
        for (int nf = 0; nf < 8; nf++) {
            int c0 = s0 + nf * 8 + qc2;
#pragma unroll
            for (int c = 0; c < 4; c++) {
                int col = c0 + (c & 1);
                int row = (c < 2) ? qrow0 : qrow1;
                bool ok = (col <= row) && (col > row - window);
                S[nf][c] = ok ? S[nf][c] * sc : -1e30f;
            }
        }

        float mx0 = -1e30f, mx1 = -1e30f;
#pragma unroll
        for (int nf = 0; nf < 8; nf++) {
            mx0 = fmaxf(mx0, fmaxf(S[nf][0], S[nf][1]));
            mx1 = fmaxf(mx1, fmaxf(S[nf][2], S[nf][3]));
        }
        mx0 = fmaxf(mx0, __shfl_xor_sync(0xffffffffu, mx0, 1));
        mx0 = fmaxf(mx0, __shfl_xor_sync(0xffffffffu, mx0, 2));
        mx1 = fmaxf(mx1, __shfl_xor_sync(0xffffffffu, mx1, 1));
        mx1 = fmaxf(mx1, __shfl_xor_sync(0xffffffffu, mx1, 2));

        float mn0 = fmaxf(m0, mx0), mn1 = fmaxf(m1, mx1);
        float corr0 = exp2f(m0 - mn0), corr1 = exp2f(m1 - mn1);
        m0 = mn0; m1 = mn1;

        uint32_t Phi[4][4], Plo[4][4];
        float rs0 = 0.0f, rs1 = 0.0f;
#pragma unroll
        for (int nf = 0; nf < 8; nf++) {
            float p0 = exp2f(S[nf][0] - mn0);
            float p1 = exp2f(S[nf][1] - mn0);
            float p2 = exp2f(S[nf][2] - mn1);
            float p3 = exp2f(S[nf][3] - mn1);
            rs0 += p0 + p1;
            rs1 += p2 + p3;
            __nv_bfloat16 h0 = __float2bfloat16(p0), h1 = __float2bfloat16(p1);
            __nv_bfloat16 h2 = __float2bfloat16(p2), h3 = __float2bfloat16(p3);
            __nv_bfloat16 e0 = __float2bfloat16(p0 - __bfloat162float(h0));
            __nv_bfloat16 e1 = __float2bfloat16(p1 - __bfloat162float(h1));
            __nv_bfloat16 e2 = __float2bfloat16(p2 - __bfloat162float(h2));
            __nv_bfloat16 e3 = __float2bfloat16(p3 - __bfloat162float(h3));
            const int kf = nf >> 1;
            if ((nf & 1) == 0) {
                Phi[kf][0] = pack2(h0, h1); Phi[kf][1] = pack2(h2, h3);
                Plo[kf][0] = pack2(e0, e1); Plo[kf][1] = pack2(e2, e3);
            } else {
                Phi[kf][2] = pack2(h0, h1); Phi[kf][3] = pack2(h2, h3);
                Plo[kf][2] = pack2(e0, e1); Plo[kf][3] = pack2(e2, e3);
            }
        }
        rs0 += __shfl_xor_sync(0xffffffffu, rs0, 1);
        rs0 += __shfl_xor_sync(0xffffffffu, rs0, 2);
        rs1 += __shfl_xor_sync(0xffffffffu, rs1, 1);
        rs1 += __shfl_xor_sync(0xffffffffu, rs1, 2);

        l0 = l0 * corr0 + rs0;
        l1 = l1 * corr1 + rs1;
#pragma unroll
        for (int nf = 0; nf < 16; nf++) {
            O[nf][0] *= corr0; O[nf][1] *= corr0;
            O[nf][2] *= corr1; O[nf][3] *= corr1;
        }

#pragma unroll
        for (int kf = 0; kf < 4; kf++) {
#pragma unroll
            for (int nt = 0; nt < 8; nt++) {
                uint32_t vh[4], vl[4];
                uint32_t voff = (kf * 16 + vkr) * AROWB + (nt * 16 + vnc) * 2;
                ldm_x4_t(vh, Vhi + voff);
                ldm_x4_t(vl, Vlo + voff);
                mma16816(O[2 * nt],     Phi[kf], vh[0], vh[1]);
                mma16816(O[2 * nt + 1], Phi[kf], vh[2], vh[3]);
                mma16816(O[2 * nt],     Phi[kf], vl[0], vl[1]);
                mma16816(O[2 * nt + 1], Phi[kf], vl[2], vl[3]);
                mma16816(O[2 * nt],     Plo[kf], vh[0], vh[1]);
                mma16816(O[2 * nt + 1], Plo[kf], vh[2], vh[3]);
            }
        }
    }

    // ---- epilogue: normalize, split to fp16 hi/lo, store ----
    const float inv0 = 1.0f / l0, inv1 = 1.0f / l1;
#pragma unroll
    for (int nf = 0; nf < 16; nf++) {
        int col = nf * 8 + qc2;
        size_t base0 = (size_t)qrow0 * HID + h * HD + col;
        size_t base1 = (size_t)qrow1 * HID + h * HD + col;
        float x0 = O[nf][0] * inv0, x1 = O[nf][1] * inv0;
        float x2 = O[nf][2] * inv1, x3 = O[nf][3] * inv1;
        __half h0 = __float2half(x0), h1 = __float2half(x1);
        __half h2 = __float2half(x2), h3 = __float2half(x3);
        *(uint32_t*)(outHi + base0) = pack2h(h0, h1);
        *(uint32_t*)(outHi + base1) = pack2h(h2, h3);
        __half e0 = __float2half(x0 - __half2float(h0));
        __half e1 = __float2half(x1 - __half2float(h1));
        __half e2 = __float2half(x2 - __half2float(h2));
        __half e3 = __float2half(x3 - __half2float(h3));
        *(uint32_t*)(outLo + base0) = pack2h(e0, e1);
        *(uint32_t*)(outLo + base1) = pack2h(e2, e3);
    }
}

// ---------------------------------------------------------------------------
extern "C" void kernel_launch(void* const* d_in, const int* in_sizes, int n_in,
                              void* d_out, int out_size)
{
    const int*   positions = (const int*)d_in[0];
    const float* hidden    = (const float*)d_in[1];
    const float* wqkv      = (const float*)d_in[2];
    const float* bqkv      = (const float*)d_in[3];
    const float* wo        = (const float*)d_in[4];
    const float* bo        = (const float*)d_in[5];
    const int*   window    = (const int*)d_in[6];
    float* out = (float*)d_out;

    float* qkv_ptr;
    __half *hid_hi, *hid_lo, *wqkv_h, *wo_h, *attn_hi, *attn_lo;
    cudaGetSymbolAddress((void**)&qkv_ptr,  g_qkv);
    cudaGetSymbolAddress((void**)&hid_hi,   g_hid_hi);
    cudaGetSymbolAddress((void**)&hid_lo,   g_hid_lo);
    cudaGetSymbolAddress((void**)&wqkv_h,   g_wqkv_h);
    cudaGetSymbolAddress((void**)&wo_h,     g_wo_h);
    cudaGetSymbolAddress((void**)&attn_hi,  g_attn_hi);
    cudaGetSymbolAddress((void**)&attn_lo,  g_attn_lo);

    cudaFuncSetAttribute(gemm_f16, cudaFuncAttributeMaxDynamicSharedMemorySize, GEMM_SMEM);
    cudaFuncSetAttribute(attn_mma, cudaFuncAttributeMaxDynamicSharedMemorySize, ATTN_SMEM);

    const int nHid  = TT * HID;
    const int nWqkv = QKVD * HID;
    const int nWo   = HID * HID;

    split_f16<<<(nHid / 4 + 255) / 256, 256>>>(hidden, hid_hi, hid_lo, nHid / 4);
    conv_f16<<<(nWqkv / 4 + 255) / 256, 256>>>(wqkv, wqkv_h, nWqkv / 4);

    gemm_f16<<<dim3(TT / GBM, QKVD / GBN), 512, GEMM_SMEM>>>(
        hid_hi, hid_lo, wqkv_h, bqkv, qkv_ptr, TT, QKVD, HID);

    rope_kernel<<<dim3(10, TT), 256>>>(qkv_ptr, positions);

    attn_mma<<<dim3(TT / 128, NH), 256, ATTN_SMEM>>>(qkv_ptr, attn_hi, attn_lo, window);

    conv_f16<<<(nWo / 4 + 255) / 256, 256>>>(wo, wo_h, nWo / 4);

    gemm_f16<<<dim3(TT / GBM, HID / GBN), 512, GEMM_SMEM>>>(
        attn_hi, attn_lo, wo_h, bo, out, TT, HID, HID);
}

// round 13
// speedup vs baseline: 1.0386x; 1.0386x over previous
#include <cuda_runtime.h>
#include <cuda_bf16.h>
#include <cuda_fp16.h>
#include <math.h>
#include <stdint.h>

#define TT 2048
#define HID 4608
#define NH 36
#define NKV 4
#define HD 128
#define QKVD 5632
#define GROUP 9
#define ATT_SCALE 0.08838834764831843f
#define LOG2E 1.4426950408889634f

// ---------------- scratch ----------------
__device__ float g_qkv[TT * QKVD];
__device__ __half g_hid_hi[TT * HID];
__device__ __half g_hid_lo[TT * HID];
__device__ __half g_wqkv_h[QKVD * HID];
__device__ __half g_wo_h[HID * HID];
__device__ __half g_attn_hi[TT * HID];
__device__ __half g_attn_lo[TT * HID];

__device__ __forceinline__ uint32_t smem_u32(const void* p) {
    uint32_t a;
    asm("{ .reg .u64 t; cvta.to.shared.u64 t, %1; cvt.u32.u64 %0, t; }" : "=r"(a) : "l"(p));
    return a;
}
__device__ __forceinline__ void ldm_x4(uint32_t* r, uint32_t addr) {
    asm volatile("ldmatrix.sync.aligned.m8n8.x4.shared.b16 {%0,%1,%2,%3}, [%4];"
                 : "=r"(r[0]), "=r"(r[1]), "=r"(r[2]), "=r"(r[3]) : "r"(addr));
}
__device__ __forceinline__ void ldm_x4_t(uint32_t* r, uint32_t addr) {
    asm volatile("ldmatrix.sync.aligned.m8n8.x4.trans.shared.b16 {%0,%1,%2,%3}, [%4];"
                 : "=r"(r[0]), "=r"(r[1]), "=r"(r[2]), "=r"(r[3]) : "r"(addr));
}
// bf16 MMA, f32 acc (attention)
__device__ __forceinline__ void mma16816(float* d, const uint32_t* a, uint32_t b0, uint32_t b1) {
    asm volatile(
        "mma.sync.aligned.m16n8k16.row.col.f32.bf16.bf16.f32 "
        "{%0,%1,%2,%3}, {%4,%5,%6,%7}, {%8,%9}, {%0,%1,%2,%3};"
        : "+f"(d[0]), "+f"(d[1]), "+f"(d[2]), "+f"(d[3])
        : "r"(a[0]), "r"(a[1]), "r"(a[2]), "r"(a[3]), "r"(b0), "r"(b1));
}
// fp16 MMA, f32 acc (GEMMs)
__device__ __forceinline__ void mma16816h(float* d, const uint32_t* a, uint32_t b0, uint32_t b1) {
    asm volatile(
        "mma.sync.aligned.m16n8k16.row.col.f32.f16.f16.f32 "
        "{%0,%1,%2,%3}, {%4,%5,%6,%7}, {%8,%9}, {%0,%1,%2,%3};"
        : "+f"(d[0]), "+f"(d[1]), "+f"(d[2]), "+f"(d[3])
        : "r"(a[0]), "r"(a[1]), "r"(a[2]), "r"(a[3]), "r"(b0), "r"(b1));
}
__device__ __forceinline__ uint32_t pack2(__nv_bfloat16 a, __nv_bfloat16 b) {
    __nv_bfloat162 t(a, b);
    return *reinterpret_cast<uint32_t*>(&t);
}
__device__ __forceinline__ uint32_t pack2h(__half a, __half b) {
    __half2 t(a, b);
    return *reinterpret_cast<uint32_t*>(&t);
}
__device__ __forceinline__ void split4(float4 v, uint2& hi, uint2& lo) {
    __nv_bfloat16 h0 = __float2bfloat16(v.x), h1 = __float2bfloat16(v.y);
    __nv_bfloat16 h2 = __float2bfloat16(v.z), h3 = __float2bfloat16(v.w);
    __nv_bfloat16 l0 = __float2bfloat16(v.x - __bfloat162float(h0));
    __nv_bfloat16 l1 = __float2bfloat16(v.y - __bfloat162float(h1));
    __nv_bfloat16 l2 = __float2bfloat16(v.z - __bfloat162float(h2));
    __nv_bfloat16 l3 = __float2bfloat16(v.w - __bfloat162float(h3));
    hi.x = pack2(h0, h1); hi.y = pack2(h2, h3);
    lo.x = pack2(l0, l1); lo.y = pack2(l2, l3);
}
__device__ __forceinline__ void split4h(float4 v, uint2& hi, uint2& lo) {
    __half h0 = __float2half(v.x), h1 = __float2half(v.y);
    __half h2 = __float2half(v.z), h3 = __float2half(v.w);
    __half l0 = __float2half(v.x - __half2float(h0));
    __half l1 = __float2half(v.y - __half2float(h1));
    __half l2 = __float2half(v.z - __half2float(h2));
    __half l3 = __float2half(v.w - __half2float(h3));
    hi.x = pack2h(h0, h1); hi.y = pack2h(h2, h3);
    lo.x = pack2h(l0, l1); lo.y = pack2h(l2, l3);
}

// ---------------------------------------------------------------------------
// fp32 -> fp16 hi/lo split (activations)
// ---------------------------------------------------------------------------
__global__ __launch_bounds__(256) void split_f16(const float* __restrict__ x,
                                                 __half* __restrict__ hi,
                                                 __half* __restrict__ lo,
                                                 int n4)
{
    int i = blockIdx.x * 256 + threadIdx.x;
    if (i >= n4) return;
    float4 v = ((const float4*)x)[i];
    uint2 H, L;
    split4h(v, H, L);
    ((uint2*)hi)[i] = H;
    ((uint2*)lo)[i] = L;
}

// fp32 -> fp16 plain convert (weights)
__global__ __launch_bounds__(256) void conv_f16(const float* __restrict__ x,
                                                __half* __restrict__ y,
                                                int n4)
{
    int i = blockIdx.x * 256 + threadIdx.x;
    if (i >= n4) return;
    float4 v = ((const float4*)x)[i];
    uint2 H;
    H.x = pack2h(__float2half(v.x), __float2half(v.y));
    H.y = pack2h(__float2half(v.z), __float2half(v.w));
    ((uint2*)y)[i] = H;
}

// ---------------------------------------------------------------------------
// fp16x2 GEMM: C = A @ B^T + bias. A hi/lo fp16, B fp16. All f32 accumulate.
// BK=128, 2 stages (209 KB smem), 512 threads.
// Rows padded to 272B (272 mod 128 = 16 -> conflict-free ldmatrix).
// ---------------------------------------------------------------------------
#define GBM 128
#define GBN 128
#define GBK 128
#define ROWB 272
#define TILE_B (128 * ROWB)         // 34816
#define STAGE_B (3 * TILE_B)        // Ahi, Alo, Bh = 104448
#define NSTG 2
#define GEMM_SMEM (NSTG * STAGE_B)  // 208896

__global__ __launch_bounds__(512, 1) void gemm_f16(
    const __half* __restrict__ Ahi, const __half* __restrict__ Alo,
    const __half* __restrict__ Bh,
    const float* __restrict__ bias, float* __restrict__ C,
    int M, int N, int K)
{
    extern __shared__ char smem[];
    const uint32_t sb = smem_u32(smem);
    const int tid = threadIdx.x, wid = tid >> 5, lane = tid & 31;
    const int warp_m = wid & 3;
    const int warp_n = wid >> 2;
    const int bm = blockIdx.x * GBM, bn = blockIdx.y * GBN;

    float acc[2][4][4];
#pragma unroll
    for (int i = 0; i < 2; i++)
#pragma unroll
        for (int j = 0; j < 4; j++)
#pragma unroll
            for (int q = 0; q < 4; q++) acc[i][j][q] = 0.0f;

    // stage loader: 3 tiles x 128 rows x 16 chunks(16B) = 6144 chunks, 12/thread
    auto load_stage = [&](int stg, int k0) {
        uint32_t base = sb + stg * STAGE_B;
#pragma unroll
        for (int i = 0; i < 12; i++) {
            int c = tid + i * 512;
            int tile = c >> 11;         // 0:Ahi 1:Alo 2:Bh
            int idx = c & 2047;
            int row = idx >> 4, ch = idx & 15;
            const __half* g;
            int grow;
            if (tile == 0) { g = Ahi; grow = bm + row; }
            else if (tile == 1) { g = Alo; grow = bm + row; }
            else { g = Bh; grow = bn + row; }
            const char* src = (const char*)(g + (size_t)grow * K + k0) + ch * 16;
            uint32_t dst = base + tile * TILE_B + row * ROWB + ch * 16;
            asm volatile("cp.async.cg.shared.global [%0], [%1], 16;" :: "r"(dst), "l"(src));
        }
        asm volatile("cp.async.commit_group;" ::: "memory");
    };

    const int NKB = K / GBK;   // 36
    load_stage(0, 0);
    load_stage(1, GBK);

    const int a_row = (lane & 15);
    const int a_kh = lane >> 4;
    const int b_nrow = (lane & 7) + ((lane >> 4) & 1) * 8;
    const int b_kh = (lane >> 3) & 1;

    for (int kb = 0; kb < NKB; kb++) {
        const int cur = kb & 1;
        if (kb + 1 < NKB) { asm volatile("cp.async.wait_group 1;" ::: "memory"); }
        else              { asm volatile("cp.async.wait_group 0;" ::: "memory"); }
        __syncthreads();

        const uint32_t stage = sb + cur * STAGE_B;
        const uint32_t Ah = stage;
        const uint32_t Al = stage + TILE_B;
        const uint32_t Bt = stage + 2 * TILE_B;

#pragma unroll
        for (int ks = 0; ks < 8; ks++) {
            uint32_t ah[2][4], al[2][4];
#pragma unroll
            for (int mf = 0; mf < 2; mf++) {
                uint32_t off = (warp_m * 32 + mf * 16 + a_row) * ROWB + ks * 32 + a_kh * 16;
                ldm_x4(ah[mf], Ah + off);
                ldm_x4(al[mf], Al + off);
            }
            uint32_t bh[2][4];
#pragma unroll
            for (int p = 0; p < 2; p++) {
                uint32_t off = (warp_n * 32 + p * 16 + b_nrow) * ROWB + ks * 32 + b_kh * 16;
                ldm_x4(bh[p], Bt + off);
            }
#pragma unroll
            for (int mf = 0; mf < 2; mf++)
#pragma unroll
                for (int nf = 0; nf < 4; nf++) {
                    const int p = nf >> 1, o = (nf & 1) * 2;
                    mma16816h(acc[mf][nf], ah[mf], bh[p][o], bh[p][o + 1]);  // Ah*B
                }
#pragma unroll
            for (int mf = 0; mf < 2; mf++)
#pragma unroll
                for (int nf = 0; nf < 4; nf++) {
                    const int p = nf >> 1, o = (nf & 1) * 2;
                    mma16816h(acc[mf][nf], al[mf], bh[p][o], bh[p][o + 1]);  // Al*B
                }
        }

        __syncthreads();   // all warps done reading 'cur' before overwriting
        if (kb + 2 < NKB) load_stage(cur, (kb + 2) * GBK);
    }

    const int qr = lane >> 2, qc = (lane & 3) * 2;
#pragma unroll
    for (int mf = 0; mf < 2; mf++) {
        int row0 = bm + warp_m * 32 + mf * 16 + qr;
#pragma unroll
        for (int nf = 0; nf < 4; nf++) {
            int col = bn + warp_n * 32 + nf * 8 + qc;
            float2 bv = *(const float2*)(bias + col);
            float2 v0 = { acc[mf][nf][0] + bv.x, acc[mf][nf][1] + bv.y };
            float2 v1 = { acc[mf][nf][2] + bv.x, acc[mf][nf][3] + bv.y };
            *(float2*)(C + (size_t)row0 * N + col) = v0;
            *(float2*)(C + (size_t)(row0 + 8) * N + col) = v1;
        }
    }
}

// ---------------------------------------------------------------------------
// NeoX RoPE (4 heads per 256-thread block)
// ---------------------------------------------------------------------------
__global__ __launch_bounds__(256) void rope_kernel(float* __restrict__ qkv,
                                                   const int* __restrict__ positions)
{
    const int tid = threadIdx.x;
    const int d = tid & 63;
    const int hh = blockIdx.x * 4 + (tid >> 6);
    const int t = blockIdx.y;

    float* base;
    if (hh < NH) base = qkv + (size_t)t * QKVD + hh * HD;
    else         base = qkv + (size_t)t * QKVD + NH * HD + (hh - NH) * HD;

    const float pos = (float)positions[t];
    const float inv_freq = expf(-11.512925464970229f * ((float)d / 64.0f));
    const float ang = pos * inv_freq;
    float s, c;
    sincosf(ang, &s, &c);

    const float x1 = base[d];
    const float x2 = base[d + 64];
    base[d]      = x1 * c - x2 * s;
    base[d + 64] = x2 * c + x1 * s;
}

// ---------------------------------------------------------------------------
// Windowed causal flash attention on HMMA (bf16x3 internally).
// Epilogue writes fp16 hi/lo for the fp16x2 output GEMM.
// ---------------------------------------------------------------------------
#define AROWB 272
#define AQ_B (128 * AROWB)
#define AK_B (64 * AROWB)
#define ATTN_SMEM (AQ_B * 2 + AK_B * 4)

__global__ __launch_bounds__(256, 1) void attn_mma(
    const float* __restrict__ qkv,
    __half* __restrict__ outHi,
    __half* __restrict__ outLo,
    const int* __restrict__ winp)
{
    extern __shared__ char smem[];
    const uint32_t sb = smem_u32(smem);
    const uint32_t Qhi = sb,                Qlo = sb + AQ_B;
    const uint32_t Khi = sb + 2 * AQ_B,     Klo = Khi + AK_B;
    const uint32_t Vhi = Klo + AK_B,        Vlo = Vhi + AK_B;

    const int tid = threadIdx.x, w = tid >> 5, lane = tid & 31;
    const int h = blockIdx.y, qt0 = blockIdx.x * 128;
    const int kvh = h / GROUP;
    const int window = *winp;
    const int g = lane >> 2, qc2 = (lane & 3) * 2;

    const size_t qOff = (size_t)h * HD;
    const size_t kOff = (size_t)NH * HD + (size_t)kvh * HD;
    const size_t vOff = kOff + (size_t)NKV * HD;

    for (int idx = tid; idx < 128 * 32; idx += 256) {
        int row = idx >> 5, c4 = idx & 31;
        float4 v = *(const float4*)(qkv + (size_t)(qt0 + row) * QKVD + qOff + c4 * 4);
        uint2 H, L;
        split4(v, H, L);
        *(uint2*)(smem + (Qhi - sb) + row * AROWB + c4 * 8) = H;
        *(uint2*)(smem + (Qlo - sb) + row * AROWB + c4 * 8) = L;
    }

    float m0 = -1e30f, m1 = -1e30f, l0 = 0.0f, l1 = 0.0f;
    float O[16][4];
#pragma unroll
    for (int i = 0; i < 16; i++)
#pragma unroll
        for (int j = 0; j < 4; j++) O[i][j] = 0.0f;

    const int a_row = (lane & 15);
    const int a_kh = lane >> 4;
    const int b_nrow = (lane & 7) + ((lane >> 4) & 1) * 8;
    const int b_kh = (lane >> 3) & 1;
    const int vkr = (lane & 7) + ((lane >> 3) & 1) * 8;
    const int vnc = ((lane >> 4) & 1) * 8;

    const float sc = ATT_SCALE * LOG2E;
    const int qrow0 = qt0 + w * 16 + g;
    const int qrow1 = qrow0 + 8;

    int sBegin = qt0 - window + 1;
    if (sBegin < 0) sBegin = 0;
    sBegin &= ~63;
    const int sEnd = qt0 + 127;

    for (int s0 = sBegin; s0 <= sEnd; s0 += 64) {
        __syncthreads();
        for (int idx = tid; idx < 64 * 32; idx += 256) {
            int row = idx >> 5, c4 = idx & 31;
            float4 kv = *(const float4*)(qkv + (size_t)(s0 + row) * QKVD + kOff + c4 * 4);
            uint2 H, L;
            split4(kv, H, L);
            *(uint2*)(smem + (Khi - sb) + row * AROWB + c4 * 8) = H;
            *(uint2*)(smem + (Klo - sb) + row * AROWB + c4 * 8) = L;
            float4 vv = *(const float4*)(qkv + (size_t)(s0 + row) * QKVD + vOff + c4 * 4);
            split4(vv, H, L);
            *(uint2*)(smem + (Vhi - sb) + row * AROWB + c4 * 8) = H;
            *(uint2*)(smem + (Vlo - sb) + row * AROWB + c4 * 8) = L;
        }
        __syncthreads();

        float S[8][4];
#pragma unroll
        for (int i = 0; i < 8; i++)
#pragma unroll
            for (int j = 0; j < 4; j++) S[i][j] = 0.0f;

#pragma unroll
        for (int kf = 0; kf < 8; kf++) {
            uint32_t ah[4], al[4];
            uint32_t aoff = (w * 16 + a_row) * AROWB + kf * 32 + a_kh * 16;
            ldm_x4(ah, Qhi + aoff);
            ldm_x4(al, Qlo + aoff);
#pragma unroll
            for (int nt = 0; nt < 4; nt++) {
                uint32_t bh[4], bl[4];
                uint32_t boff = (nt * 16 + b_nrow) * AROWB + kf * 32 + b_kh * 16;
                ldm_x4(bh, Khi + boff);
                ldm_x4(bl, Klo + boff);
                mma16816(S[2 * nt],     ah, bh[0], bh[1]);
                mma16816(S[2 * nt + 1], ah, bh[2], bh[3]);
                mma16816(S[2 * nt],     ah, bl[0], bl[1]);
                mma16816(S[2 * nt + 1], ah, bl[2], bl[3]);
                mma16816(S[2 * nt],     al, bh[0], bh[1]);
                mma16816(S[2 * nt + 1], al, bh[2], bh[3]);
            }
        }

#pragma unroll
        for (int nf = 0; nf < 8; nf++) {
            int c0 = s0 + nf * 8 + qc2;
#pragma unroll
            for (int c = 0; c < 4; c++) {
                int col = c0 + (c & 1);
                int row = (c < 2) ? qrow0 : qrow1;
                bool ok = (col <= row) && (col > row - window);
                S[nf][c] = ok ? S[nf][c] * sc : -1e30f;
            }
        }

        float mx0 = -1e30f, mx1 = -1e30f;
#pragma unroll
        for (int nf = 0; nf < 8; nf++) {
            mx0 = fmaxf(mx0, fmaxf(S[nf][0], S[nf][1]));
            mx1 = fmaxf(mx1, fmaxf(S[nf][2], S[nf][3]));
        }
        mx0 = fmaxf(mx0, __shfl_xor_sync(0xffffffffu, mx0, 1));
        mx0 = fmaxf(mx0, __shfl_xor_sync(0xffffffffu, mx0, 2));
        mx1 = fmaxf(mx1, __shfl_xor_sync(0xffffffffu, mx1, 1));
        mx1 = fmaxf(mx1, __shfl_xor_sync(0xffffffffu, mx1, 2));

        float mn0 = fmaxf(m0, mx0), mn1 = fmaxf(m1, mx1);
        float corr0 = exp2f(m0 - mn0), corr1 = exp2f(m1 - mn1);
        m0 = mn0; m1 = mn1;

        uint32_t Phi[4][4], Plo[4][4];
        float rs0 = 0.0f, rs1 = 0.0f;
#pragma unroll
        for (int nf = 0; nf < 8; nf++) {
            float p0 = exp2f(S[nf][0] - mn0);
            float p1 = exp2f(S[nf][1] - mn0);
            float p2 = exp2f(S[nf][2] - mn1);
            float p3 = exp2f(S[nf][3] - mn1);
            rs0 += p0 + p1;
            rs1 += p2 + p3;
            __nv_bfloat16 h0 = __float2bfloat16(p0), h1 = __float2bfloat16(p1);
            __nv_bfloat16 h2 = __float2bfloat16(p2), h3 = __float2bfloat16(p3);
            __nv_bfloat16 e0 = __float2bfloat16(p0 - __bfloat162float(h0));
            __nv_bfloat16 e1 = __float2bfloat16(p1 - __bfloat162float(h1));
            __nv_bfloat16 e2 = __float2bfloat16(p2 - __bfloat162float(h2));
            __nv_bfloat16 e3 = __float2bfloat16(p3 - __bfloat162float(h3));
            const int kf = nf >> 1;
            if ((nf & 1) == 0) {
                Phi[kf][0] = pack2(h0, h1); Phi[kf][1] = pack2(h2, h3);
                Plo[kf][0] = pack2(e0, e1); Plo[kf][1] = pack2(e2, e3);
            } else {
                Phi[kf][2] = pack2(h0, h1); Phi[kf][3] = pack2(h2, h3);
                Plo[kf][2] = pack2(e0, e1); Plo[kf][3] = pack2(e2, e3);
            }
        }
        rs0 += __shfl_xor_sync(0xffffffffu, rs0, 1);
        rs0 += __shfl_xor_sync(0xffffffffu, rs0, 2);
        rs1 += __shfl_xor_sync(0xffffffffu, rs1, 1);
        rs1 += __shfl_xor_sync(0xffffffffu, rs1, 2);

        l0 = l0 * corr0 + rs0;
        l1 = l1 * corr1 + rs1;
#pragma unroll
        for (int nf = 0; nf < 16; nf++) {
            O[nf][0] *= corr0; O[nf][1] *= corr0;
            O[nf][2] *= corr1; O[nf][3] *= corr1;
        }

#pragma unroll
        for (int kf = 0; kf < 4; kf++) {
#pragma unroll
            for (int nt = 0; nt < 8; nt++) {
                uint32_t vh[4], vl[4];
                uint32_t voff = (kf * 16 + vkr) * AROWB + (nt * 16 + vnc) * 2;
                ldm_x4_t(vh, Vhi + voff);
                ldm_x4_t(vl, Vlo + voff);
                mma16816(O[2 * nt],     Phi[kf], vh[0], vh[1]);
                mma16816(O[2 * nt + 1], Phi[kf], vh[2], vh[3]);
                mma16816(O[2 * nt],     Phi[kf], vl[0], vl[1]);
                mma16816(O[2 * nt + 1], Phi[kf], vl[2], vl[3]);
                mma16816(O[2 * nt],     Plo[kf], vh[0], vh[1]);
                mma16816(O[2 * nt + 1], Plo[kf], vh[2], vh[3]);
            }
        }
    }

    // ---- epilogue: normalize, split to fp16 hi/lo, store ----
    const float inv0 = 1.0f / l0, inv1 = 1.0f / l1;
#pragma unroll
    for (int nf = 0; nf < 16; nf++) {
        int col = nf * 8 + qc2;
        size_t base0 = (size_t)qrow0 * HID + h * HD + col;
        size_t base1 = (size_t)qrow1 * HID + h * HD + col;
        float x0 = O[nf][0] * inv0, x1 = O[nf][1] * inv0;
        float x2 = O[nf][2] * inv1, x3 = O[nf][3] * inv1;
        __half h0 = __float2half(x0), h1 = __float2half(x1);
        __half h2 = __float2half(x2), h3 = __float2half(x3);
        *(uint32_t*)(outHi + base0) = pack2h(h0, h1);
        *(uint32_t*)(outHi + base1) = pack2h(h2, h3);
        __half e0 = __float2half(x0 - __half2float(h0));
        __half e1 = __float2half(x1 - __half2float(h1));
        __half e2 = __float2half(x2 - __half2float(h2));
        __half e3 = __float2half(x3 - __half2float(h3));
        *(uint32_t*)(outLo + base0) = pack2h(e0, e1);
        *(uint32_t*)(outLo + base1) = pack2h(e2, e3);
    }
}

// ---------------------------------------------------------------------------
extern "C" void kernel_launch(void* const* d_in, const int* in_sizes, int n_in,
                              void* d_out, int out_size)
{
    const int*   positions = (const int*)d_in[0];
    const float* hidden    = (const float*)d_in[1];
    const float* wqkv      = (const float*)d_in[2];
    const float* bqkv      = (const float*)d_in[3];
    const float* wo        = (const float*)d_in[4];
    const float* bo        = (const float*)d_in[5];
    const int*   window    = (const int*)d_in[6];
    float* out = (float*)d_out;

    float* qkv_ptr;
    __half *hid_hi, *hid_lo, *wqkv_h, *wo_h, *attn_hi, *attn_lo;
    cudaGetSymbolAddress((void**)&qkv_ptr,  g_qkv);
    cudaGetSymbolAddress((void**)&hid_hi,   g_hid_hi);
    cudaGetSymbolAddress((void**)&hid_lo,   g_hid_lo);
    cudaGetSymbolAddress((void**)&wqkv_h,   g_wqkv_h);
    cudaGetSymbolAddress((void**)&wo_h,     g_wo_h);
    cudaGetSymbolAddress((void**)&attn_hi,  g_attn_hi);
    cudaGetSymbolAddress((void**)&attn_lo,  g_attn_lo);

    cudaFuncSetAttribute(gemm_f16, cudaFuncAttributeMaxDynamicSharedMemorySize, GEMM_SMEM);
    cudaFuncSetAttribute(attn_mma, cudaFuncAttributeMaxDynamicSharedMemorySize, ATTN_SMEM);

    const int nHid  = TT * HID;
    const int nWqkv = QKVD * HID;
    const int nWo   = HID * HID;

    split_f16<<<(nHid / 4 + 255) / 256, 256>>>(hidden, hid_hi, hid_lo, nHid / 4);
    conv_f16<<<(nWqkv / 4 + 255) / 256, 256>>>(wqkv, wqkv_h, nWqkv / 4);

    gemm_f16<<<dim3(TT / GBM, QKVD / GBN), 512, GEMM_SMEM>>>(
        hid_hi, hid_lo, wqkv_h, bqkv, qkv_ptr, TT, QKVD, HID);

    rope_kernel<<<dim3(10, TT), 256>>>(qkv_ptr, positions);

    attn_mma<<<dim3(TT / 128, NH), 256, ATTN_SMEM>>>(qkv_ptr, attn_hi, attn_lo, window);

    conv_f16<<<(nWo / 4 + 255) / 256, 256>>>(wo, wo_h, nWo / 4);

    gemm_f16<<<dim3(TT / GBM, HID / GBN), 512, GEMM_SMEM>>>(
        attn_hi, attn_lo, wo_h, bo, out, TT, HID, HID);
}

// round 15
// speedup vs baseline: 1.1061x; 1.0650x over previous
#include <cuda_runtime.h>
#include <cuda_bf16.h>
#include <cuda_fp16.h>
#include <math.h>
#include <stdint.h>

#define TT 2048
#define HID 4608
#define NH 36
#define NKV 4
#define HD 128
#define QKVD 5632
#define GROUP 9
#define ATT_SCALE 0.08838834764831843f
#define LOG2E 1.4426950408889634f

// ---------------- scratch ----------------
__device__ float g_qkv[TT * QKVD];
__device__ __nv_bfloat16 g_qkv_hi[TT * QKVD];
__device__ __nv_bfloat16 g_qkv_lo[TT * QKVD];
__device__ __half g_hid_hi[TT * HID];
__device__ __half g_hid_lo[TT * HID];
__device__ __half g_wqkv_h[QKVD * HID];
__device__ __half g_wo_h[HID * HID];
__device__ __half g_attn_hi[TT * HID];
__device__ __half g_attn_lo[TT * HID];

__device__ __forceinline__ uint32_t smem_u32(const void* p) {
    uint32_t a;
    asm("{ .reg .u64 t; cvta.to.shared.u64 t, %1; cvt.u32.u64 %0, t; }" : "=r"(a) : "l"(p));
    return a;
}
__device__ __forceinline__ float ex2(float x) {
    float r;
    asm("ex2.approx.f32 %0, %1;" : "=f"(r) : "f"(x));
    return r;
}
__device__ __forceinline__ void ldm_x4(uint32_t* r, uint32_t addr) {
    asm volatile("ldmatrix.sync.aligned.m8n8.x4.shared.b16 {%0,%1,%2,%3}, [%4];"
                 : "=r"(r[0]), "=r"(r[1]), "=r"(r[2]), "=r"(r[3]) : "r"(addr));
}
__device__ __forceinline__ void ldm_x4_t(uint32_t* r, uint32_t addr) {
    asm volatile("ldmatrix.sync.aligned.m8n8.x4.trans.shared.b16 {%0,%1,%2,%3}, [%4];"
                 : "=r"(r[0]), "=r"(r[1]), "=r"(r[2]), "=r"(r[3]) : "r"(addr));
}
// bf16 MMA, f32 acc (attention)
__device__ __forceinline__ void mma16816(float* d, const uint32_t* a, uint32_t b0, uint32_t b1) {
    asm volatile(
        "mma.sync.aligned.m16n8k16.row.col.f32.bf16.bf16.f32 "
        "{%0,%1,%2,%3}, {%4,%5,%6,%7}, {%8,%9}, {%0,%1,%2,%3};"
        : "+f"(d[0]), "+f"(d[1]), "+f"(d[2]), "+f"(d[3])
        : "r"(a[0]), "r"(a[1]), "r"(a[2]), "r"(a[3]), "r"(b0), "r"(b1));
}
// fp16 MMA, f32 acc (GEMMs)
__device__ __forceinline__ void mma16816h(float* d, const uint32_t* a, uint32_t b0, uint32_t b1) {
    asm volatile(
        "mma.sync.aligned.m16n8k16.row.col.f32.f16.f16.f32 "
        "{%0,%1,%2,%3}, {%4,%5,%6,%7}, {%8,%9}, {%0,%1,%2,%3};"
        : "+f"(d[0]), "+f"(d[1]), "+f"(d[2]), "+f"(d[3])
        : "r"(a[0]), "r"(a[1]), "r"(a[2]), "r"(a[3]), "r"(b0), "r"(b1));
}
__device__ __forceinline__ uint32_t pack2(__nv_bfloat16 a, __nv_bfloat16 b) {
    __nv_bfloat162 t(a, b);
    return *reinterpret_cast<uint32_t*>(&t);
}
__device__ __forceinline__ uint32_t pack2h(__half a, __half b) {
    __half2 t(a, b);
    return *reinterpret_cast<uint32_t*>(&t);
}
__device__ __forceinline__ void split4(float4 v, uint2& hi, uint2& lo) {
    __nv_bfloat16 h0 = __float2bfloat16(v.x), h1 = __float2bfloat16(v.y);
    __nv_bfloat16 h2 = __float2bfloat16(v.z), h3 = __float2bfloat16(v.w);
    __nv_bfloat16 l0 = __float2bfloat16(v.x - __bfloat162float(h0));
    __nv_bfloat16 l1 = __float2bfloat16(v.y - __bfloat162float(h1));
    __nv_bfloat16 l2 = __float2bfloat16(v.z - __bfloat162float(h2));
    __nv_bfloat16 l3 = __float2bfloat16(v.w - __bfloat162float(h3));
    hi.x = pack2(h0, h1); hi.y = pack2(h2, h3);
    lo.x = pack2(l0, l1); lo.y = pack2(l2, l3);
}
__device__ __forceinline__ void split4h(float4 v, uint2& hi, uint2& lo) {
    __half h0 = __float2half(v.x), h1 = __float2half(v.y);
    __half h2 = __float2half(v.z), h3 = __float2half(v.w);
    __half l0 = __float2half(v.x - __half2float(h0));
    __half l1 = __float2half(v.y - __half2float(h1));
    __half l2 = __float2half(v.z - __half2float(h2));
    __half l3 = __float2half(v.w - __half2float(h3));
    hi.x = pack2h(h0, h1); hi.y = pack2h(h2, h3);
    lo.x = pack2h(l0, l1); lo.y = pack2h(l2, l3);
}

// ---------------------------------------------------------------------------
// fp32 -> fp16 hi/lo split (activations for GEMMs)
// ---------------------------------------------------------------------------
__global__ __launch_bounds__(256) void split_f16(const float* __restrict__ x,
                                                 __half* __restrict__ hi,
                                                 __half* __restrict__ lo,
                                                 int n4)
{
    int i = blockIdx.x * 256 + threadIdx.x;
    if (i >= n4) return;
    float4 v = ((const float4*)x)[i];
    uint2 H, L;
    split4h(v, H, L);
    ((uint2*)hi)[i] = H;
    ((uint2*)lo)[i] = L;
}

// fp32 -> bf16 hi/lo split (qkv preconversion for attention)
__global__ __launch_bounds__(256) void split_bf(const float* __restrict__ x,
                                                __nv_bfloat16* __restrict__ hi,
                                                __nv_bfloat16* __restrict__ lo,
                                                int n4)
{
    int i = blockIdx.x * 256 + threadIdx.x;
    if (i >= n4) return;
    float4 v = ((const float4*)x)[i];
    uint2 H, L;
    split4(v, H, L);
    ((uint2*)hi)[i] = H;
    ((uint2*)lo)[i] = L;
}

// fp32 -> fp16 plain convert (weights)
__global__ __launch_bounds__(256) void conv_f16(const float* __restrict__ x,
                                                __half* __restrict__ y,
                                                int n4)
{
    int i = blockIdx.x * 256 + threadIdx.x;
    if (i >= n4) return;
    float4 v = ((const float4*)x)[i];
    uint2 H;
    H.x = pack2h(__float2half(v.x), __float2half(v.y));
    H.y = pack2h(__float2half(v.z), __float2half(v.w));
    ((uint2*)y)[i] = H;
}

// ---------------------------------------------------------------------------
// fp16x2 GEMM (round-10 proven: BK=64, 3-stage, all f32 acc, 512 threads)
// ---------------------------------------------------------------------------
#define GBM 128
#define GBN 128
#define GBK 64
#define ROWB 144
#define TILE_B (128 * ROWB)
#define STAGE_B (3 * TILE_B)
#define NSTG 3
#define GEMM_SMEM (NSTG * STAGE_B)

__global__ __launch_bounds__(512, 1) void gemm_f16(
    const __half* __restrict__ Ahi, const __half* __restrict__ Alo,
    const __half* __restrict__ Bh,
    const float* __restrict__ bias, float* __restrict__ C,
    int M, int N, int K)
{
    extern __shared__ char smem[];
    const uint32_t sb = smem_u32(smem);
    const int tid = threadIdx.x, wid = tid >> 5, lane = tid & 31;
    const int warp_m = wid & 3;
    const int warp_n = wid >> 2;
    const int bm = blockIdx.x * GBM, bn = blockIdx.y * GBN;

    float acc[2][4][4];
#pragma unroll
    for (int i = 0; i < 2; i++)
#pragma unroll
        for (int j = 0; j < 4; j++)
#pragma unroll
            for (int q = 0; q < 4; q++) acc[i][j][q] = 0.0f;

    auto load_stage = [&](int stg, int k0) {
        uint32_t base = sb + stg * STAGE_B;
#pragma unroll
        for (int i = 0; i < 6; i++) {
            int c = tid + i * 512;
            int tile = c >> 10;
            int idx = c & 1023;
            int row = idx >> 3, ch = idx & 7;
            const __half* g;
            int grow;
            if (tile == 0) { g = Ahi; grow = bm + row; }
            else if (tile == 1) { g = Alo; grow = bm + row; }
            else { g = Bh; grow = bn + row; }
            const char* src = (const char*)(g + (size_t)grow * K + k0) + ch * 16;
            uint32_t dst = base + tile * TILE_B + row * ROWB + ch * 16;
            asm volatile("cp.async.cg.shared.global [%0], [%1], 16;" :: "r"(dst), "l"(src));
        }
        asm volatile("cp.async.commit_group;" ::: "memory");
    };

    const int NKB = K / GBK;
    load_stage(0, 0);
    load_stage(1, GBK);

    const int a_row = (lane & 15);
    const int a_kh = lane >> 4;
    const int b_nrow = (lane & 7) + ((lane >> 4) & 1) * 8;
    const int b_kh = (lane >> 3) & 1;

    for (int kb = 0; kb < NKB; kb++) {
        const int cur = kb % NSTG;
        if (kb + 1 < NKB) { asm volatile("cp.async.wait_group 1;" ::: "memory"); }
        else              { asm volatile("cp.async.wait_group 0;" ::: "memory"); }
        __syncthreads();

        if (kb + 2 < NKB) load_stage((kb + 2) % NSTG, (kb + 2) * GBK);

        const uint32_t stage = sb + cur * STAGE_B;
        const uint32_t Ah = stage;
        const uint32_t Al = stage + TILE_B;
        const uint32_t Bt = stage + 2 * TILE_B;

#pragma unroll
        for (int ks = 0; ks < 4; ks++) {
            uint32_t ah[2][4], al[2][4];
#pragma unroll
            for (int mf = 0; mf < 2; mf++) {
                uint32_t off = (warp_m * 32 + mf * 16 + a_row) * ROWB + ks * 32 + a_kh * 16;
                ldm_x4(ah[mf], Ah + off);
                ldm_x4(al[mf], Al + off);
            }
            uint32_t bh[2][4];
#pragma unroll
            for (int p = 0; p < 2; p++) {
                uint32_t off = (warp_n * 32 + p * 16 + b_nrow) * ROWB + ks * 32 + b_kh * 16;
                ldm_x4(bh[p], Bt + off);
            }
#pragma unroll
            for (int mf = 0; mf < 2; mf++)
#pragma unroll
                for (int nf = 0; nf < 4; nf++) {
                    const int p = nf >> 1, o = (nf & 1) * 2;
                    mma16816h(acc[mf][nf], ah[mf], bh[p][o], bh[p][o + 1]);  // Ah*B
                }
#pragma unroll
            for (int mf = 0; mf < 2; mf++)
#pragma unroll
                for (int nf = 0; nf < 4; nf++) {
                    const int p = nf >> 1, o = (nf & 1) * 2;
                    mma16816h(acc[mf][nf], al[mf], bh[p][o], bh[p][o + 1]);  // Al*B
                }
        }
    }

    const int qr = lane >> 2, qc = (lane & 3) * 2;
#pragma unroll
    for (int mf = 0; mf < 2; mf++) {
        int row0 = bm + warp_m * 32 + mf * 16 + qr;
#pragma unroll
        for (int nf = 0; nf < 4; nf++) {
            int col = bn + warp_n * 32 + nf * 8 + qc;
            float2 bv = *(const float2*)(bias + col);
            float2 v0 = { acc[mf][nf][0] + bv.x, acc[mf][nf][1] + bv.y };
            float2 v1 = { acc[mf][nf][2] + bv.x, acc[mf][nf][3] + bv.y };
            *(float2*)(C + (size_t)row0 * N + col) = v0;
            *(float2*)(C + (size_t)(row0 + 8) * N + col) = v1;
        }
    }
}

// ---------------------------------------------------------------------------
// NeoX RoPE (4 heads per 256-thread block)
// ---------------------------------------------------------------------------
__global__ __launch_bounds__(256) void rope_kernel(float* __restrict__ qkv,
                                                   const int* __restrict__ positions)
{
    const int tid = threadIdx.x;
    const int d = tid & 63;
    const int hh = blockIdx.x * 4 + (tid >> 6);
    const int t = blockIdx.y;

    float* base;
    if (hh < NH) base = qkv + (size_t)t * QKVD + hh * HD;
    else         base = qkv + (size_t)t * QKVD + NH * HD + (hh - NH) * HD;

    const float pos = (float)positions[t];
    const float inv_freq = expf(-11.512925464970229f * ((float)d / 64.0f));
    const float ang = pos * inv_freq;
    float s, c;
    sincosf(ang, &s, &c);

    const float x1 = base[d];
    const float x2 = base[d + 64];
    base[d]      = x1 * c - x2 * s;
    base[d + 64] = x2 * c + x1 * s;
}

// ---------------------------------------------------------------------------
// Windowed causal flash attention on HMMA (bf16x3).
// Q/K/V read from preconverted bf16 hi/lo arrays via cp.async (2-stage KV ring).
// Epilogue writes fp16 hi/lo for the fp16x2 output GEMM.
// ---------------------------------------------------------------------------
#define AROWB 272
#define AQ_B (128 * AROWB)         // 34816
#define AK_B (64 * AROWB)          // 17408
#define KVSTG (4 * AK_B)           // 69632: Khi,Klo,Vhi,Vlo
#define ATTN_SMEM (2 * AQ_B + 2 * KVSTG)  // 208896

__global__ __launch_bounds__(256, 1) void attn_mma(
    const __nv_bfloat16* __restrict__ qhi,
    const __nv_bfloat16* __restrict__ qlo,
    __half* __restrict__ outHi,
    __half* __restrict__ outLo,
    const int* __restrict__ winp)
{
    extern __shared__ char smem[];
    const uint32_t sb = smem_u32(smem);
    const uint32_t Qhi = sb, Qlo = sb + AQ_B;
    const uint32_t KV0 = sb + 2 * AQ_B;

    const int tid = threadIdx.x, w = tid >> 5, lane = tid & 31;
    const int h = blockIdx.y, qt0 = blockIdx.x * 128;
    const int kvh = h / GROUP;
    const int window = *winp;
    const int g = lane >> 2, qc2 = (lane & 3) * 2;

    const size_t qOff = (size_t)h * HD;
    const size_t kOff = (size_t)NH * HD + (size_t)kvh * HD;
    const size_t vOff = kOff + (size_t)NKV * HD;

    int sBegin = qt0 - window + 1;
    if (sBegin < 0) sBegin = 0;
    sBegin &= ~63;
    const int nIter = (qt0 + 128 - sBegin) / 64;

    // KV stage loader: 4 tiles x 64 rows x 16 chunks(16B) = 4096, 16/thread
    auto load_kv = [&](int stg, int s0) {
        uint32_t base = KV0 + stg * KVSTG;
#pragma unroll
        for (int i = 0; i < 16; i++) {
            int c = tid + i * 256;
            int t_ = c >> 10;           // 0:Khi 1:Klo 2:Vhi 3:Vlo
            int idx = c & 1023;
            int row = idx >> 4, ch = idx & 15;
            const __nv_bfloat16* gp = (t_ & 1) ? qlo : qhi;
            size_t off = (t_ >= 2) ? vOff : kOff;
            const char* src = (const char*)(gp + (size_t)(s0 + row) * QKVD + off) + ch * 16;
            uint32_t dst = base + t_ * AK_B + row * AROWB + ch * 16;
            asm volatile("cp.async.cg.shared.global [%0], [%1], 16;" :: "r"(dst), "l"(src));
        }
        asm volatile("cp.async.commit_group;" ::: "memory");
    };

    // Q load (2 tiles x 128 rows x 16 chunks = 4096, 16/thread); joins group 0
#pragma unroll
    for (int i = 0; i < 16; i++) {
        int c = tid + i * 256;
        int t_ = c >> 11;               // 0:hi 1:lo
        int idx = c & 2047;
        int row = idx >> 4, ch = idx & 15;
        const __nv_bfloat16* gp = t_ ? qlo : qhi;
        const char* src = (const char*)(gp + (size_t)(qt0 + row) * QKVD + qOff) + ch * 16;
        uint32_t dst = (t_ ? Qlo : Qhi) + row * AROWB + ch * 16;
        asm volatile("cp.async.cg.shared.global [%0], [%1], 16;" :: "r"(dst), "l"(src));
    }
    load_kv(0, sBegin);                 // commits group 0 (Q + KV stage 0)
    if (nIter > 1) load_kv(1, sBegin + 64);

    float m0 = -1e30f, m1 = -1e30f, l0 = 0.0f, l1 = 0.0f;
    float O[16][4];
#pragma unroll
    for (int i = 0; i < 16; i++)
#pragma unroll
        for (int j = 0; j < 4; j++) O[i][j] = 0.0f;

    const int a_row = (lane & 15);
    const int a_kh = lane >> 4;
    const int b_nrow = (lane & 7) + ((lane >> 4) & 1) * 8;
    const int b_kh = (lane >> 3) & 1;
    const int vkr = (lane & 7) + ((lane >> 3) & 1) * 8;
    const int vnc = ((lane >> 4) & 1) * 8;

    const float sc = ATT_SCALE * LOG2E;
    const int qrow0 = qt0 + w * 16 + g;
    const int qrow1 = qrow0 + 8;

    int it = 0;
    for (int s0 = sBegin; it < nIter; s0 += 64, it++) {
        if (it + 1 < nIter) { asm volatile("cp.async.wait_group 1;" ::: "memory"); }
        else                { asm volatile("cp.async.wait_group 0;" ::: "memory"); }
        __syncthreads();

        const int cur = it & 1;
        const uint32_t Khi = KV0 + cur * KVSTG;
        const uint32_t Klo = Khi + AK_B;
        const uint32_t Vhi = Khi + 2 * AK_B;
        const uint32_t Vlo = Khi + 3 * AK_B;

        // ---- S = Q K^T ----
        float S[8][4];
#pragma unroll
        for (int i = 0; i < 8; i++)
#pragma unroll
            for (int j = 0; j < 4; j++) S[i][j] = 0.0f;

#pragma unroll
        for (int kf = 0; kf < 8; kf++) {
            uint32_t ah[4], al[4];
            uint32_t aoff = (w * 16 + a_row) * AROWB + kf * 32 + a_kh * 16;
            ldm_x4(ah, Qhi + aoff);
            ldm_x4(al, Qlo + aoff);
#pragma unroll
            for (int nt = 0; nt < 4; nt++) {
                uint32_t bh[4], bl[4];
                uint32_t boff = (nt * 16 + b_nrow) * AROWB + kf * 32 + b_kh * 16;
                ldm_x4(bh, Khi + boff);
                ldm_x4(bl, Klo + boff);
                mma16816(S[2 * nt],     ah, bh[0], bh[1]);
                mma16816(S[2 * nt + 1], ah, bh[2], bh[3]);
                mma16816(S[2 * nt],     ah, bl[0], bl[1]);
                mma16816(S[2 * nt + 1], ah, bl[2], bl[3]);
                mma16816(S[2 * nt],     al, bh[0], bh[1]);
                mma16816(S[2 * nt + 1], al, bh[2], bh[3]);
            }
        }

        // ---- scale + mask (log2 domain) ----
#pragma unroll
        for (int nf = 0; nf < 8; nf++) {
            int c0 = s0 + nf * 8 + qc2;
#pragma unroll
            for (int c = 0; c < 4; c++) {
                int col = c0 + (c & 1);
                int row = (c < 2) ? qrow0 : qrow1;
                bool ok = (col <= row) && (col > row - window);
                S[nf][c] = ok ? S[nf][c] * sc : -1e30f;
            }
        }

        // ---- online softmax ----
        float mx0 = -1e30f, mx1 = -1e30f;
#pragma unroll
        for (int nf = 0; nf < 8; nf++) {
            mx0 = fmaxf(mx0, fmaxf(S[nf][0], S[nf][1]));
            mx1 = fmaxf(mx1, fmaxf(S[nf][2], S[nf][3]));
        }
        mx0 = fmaxf(mx0, __shfl_xor_sync(0xffffffffu, mx0, 1));
        mx0 = fmaxf(mx0, __shfl_xor_sync(0xffffffffu, mx0, 2));
        mx1 = fmaxf(mx1, __shfl_xor_sync(0xffffffffu, mx1, 1));
        mx1 = fmaxf(mx1, __shfl_xor_sync(0xffffffffu, mx1, 2));

        float mn0 = fmaxf(m0, mx0), mn1 = fmaxf(m1, mx1);
        float corr0 = ex2(m0 - mn0), corr1 = ex2(m1 - mn1);
        m0 = mn0; m1 = mn1;

        uint32_t Phi[4][4], Plo[4][4];
        float rs0 = 0.0f, rs1 = 0.0f;
#pragma unroll
        for (int nf = 0; nf < 8; nf++) {
            float p0 = ex2(S[nf][0] - mn0);
            float p1 = ex2(S[nf][1] - mn0);
            float p2 = ex2(S[nf][2] - mn1);
            float p3 = ex2(S[nf][3] - mn1);
            rs0 += p0 + p1;
            rs1 += p2 + p3;
            __nv_bfloat16 h0 = __float2bfloat16(p0), h1 = __float2bfloat16(p1);
            __nv_bfloat16 h2 = __float2bfloat16(p2), h3 = __float2bfloat16(p3);
            __nv_bfloat16 e0 = __float2bfloat16(p0 - __bfloat162float(h0));
            __nv_bfloat16 e1 = __float2bfloat16(p1 - __bfloat162float(h1));
            __nv_bfloat16 e2 = __float2bfloat16(p2 - __bfloat162float(h2));
            __nv_bfloat16 e3 = __float2bfloat16(p3 - __bfloat162float(h3));
            const int kf = nf >> 1;
            if ((nf & 1) == 0) {
                Phi[kf][0] = pack2(h0, h1); Phi[kf][1] = pack2(h2, h3);
                Plo[kf][0] = pack2(e0, e1); Plo[kf][1] = pack2(e2, e3);
            } else {
                Phi[kf][2] = pack2(h0, h1); Phi[kf][3] = pack2(h2, h3);
                Plo[kf][2] = pack2(e0, e1); Plo[kf][3] = pack2(e2, e3);
            }
        }
        rs0 += __shfl_xor_sync(0xffffffffu, rs0, 1);
        rs0 += __shfl_xor_sync(0xffffffffu, rs0, 2);
        rs1 += __shfl_xor_sync(0xffffffffu, rs1, 1);
        rs1 += __shfl_xor_sync(0xffffffffu, rs1, 2);

        l0 = l0 * corr0 + rs0;
        l1 = l1 * corr1 + rs1;
#pragma unroll
        for (int nf = 0; nf < 16; nf++) {
            O[nf][0] *= corr0; O[nf][1] *= corr0;
            O[nf][2] *= corr1; O[nf][3] *= corr1;
        }

        // ---- O += P V ----
#pragma unroll
        for (int kf = 0; kf < 4; kf++) {
#pragma unroll
            for (int nt = 0; nt < 8; nt++) {
                uint32_t vh[4], vl[4];
                uint32_t voff = (kf * 16 + vkr) * AROWB + (nt * 16 + vnc) * 2;
                ldm_x4_t(vh, Vhi + voff);
                ldm_x4_t(vl, Vlo + voff);
                mma16816(O[2 * nt],     Phi[kf], vh[0], vh[1]);
                mma16816(O[2 * nt + 1], Phi[kf], vh[2], vh[3]);
                mma16816(O[2 * nt],     Phi[kf], vl[0], vl[1]);
                mma16816(O[2 * nt + 1], Phi[kf], vl[2], vl[3]);
                mma16816(O[2 * nt],     Plo[kf], vh[0], vh[1]);
                mma16816(O[2 * nt + 1], Plo[kf], vh[2], vh[3]);
            }
        }

        __syncthreads();   // all warps done with stage 'cur' before refill
        if (it + 2 < nIter) load_kv(cur, s0 + 128);
    }

    // ---- epilogue: normalize, split to fp16 hi/lo, store ----
    const float inv0 = 1.0f / l0, inv1 = 1.0f / l1;
#pragma unroll
    for (int nf = 0; nf < 16; nf++) {
        int col = nf * 8 + qc2;
        size_t base0 = (size_t)qrow0 * HID + h * HD + col;
        size_t base1 = (size_t)qrow1 * HID + h * HD + col;
        float x0 = O[nf][0] * inv0, x1 = O[nf][1] * inv0;
        float x2 = O[nf][2] * inv1, x3 = O[nf][3] * inv1;
        __half h0 = __float2half(x0), h1 = __float2half(x1);
        __half h2 = __float2half(x2), h3 = __float2half(x3);
        *(uint32_t*)(outHi + base0) = pack2h(h0, h1);
        *(uint32_t*)(outHi + base1) = pack2h(h2, h3);
        __half e0 = __float2half(x0 - __half2float(h0));
        __half e1 = __float2half(x1 - __half2float(h1));
        __half e2 = __float2half(x2 - __half2float(h2));
        __half e3 = __float2half(x3 - __half2float(h3));
        *(uint32_t*)(outLo + base0) = pack2h(e0, e1);
        *(uint32_t*)(outLo + base1) = pack2h(e2, e3);
    }
}

// ---------------------------------------------------------------------------
extern "C" void kernel_launch(void* const* d_in, const int* in_sizes, int n_in,
                              void* d_out, int out_size)
{
    const int*   positions = (const int*)d_in[0];
    const float* hidden    = (const float*)d_in[1];
    const float* wqkv      = (const float*)d_in[2];
    const float* bqkv      = (const float*)d_in[3];
    const float* wo        = (const float*)d_in[4];
    const float* bo        = (const float*)d_in[5];
    const int*   window    = (const int*)d_in[6];
    float* out = (float*)d_out;

    float* qkv_ptr;
    __nv_bfloat16 *qkv_hi, *qkv_lo;
    __half *hid_hi, *hid_lo, *wqkv_h, *wo_h, *attn_hi, *attn_lo;
    cudaGetSymbolAddress((void**)&qkv_ptr,  g_qkv);
    cudaGetSymbolAddress((void**)&qkv_hi,   g_qkv_hi);
    cudaGetSymbolAddress((void**)&qkv_lo,   g_qkv_lo);
    cudaGetSymbolAddress((void**)&hid_hi,   g_hid_hi);
    cudaGetSymbolAddress((void**)&hid_lo,   g_hid_lo);
    cudaGetSymbolAddress((void**)&wqkv_h,   g_wqkv_h);
    cudaGetSymbolAddress((void**)&wo_h,     g_wo_h);
    cudaGetSymbolAddress((void**)&attn_hi,  g_attn_hi);
    cudaGetSymbolAddress((void**)&attn_lo,  g_attn_lo);

    cudaFuncSetAttribute(gemm_f16, cudaFuncAttributeMaxDynamicSharedMemorySize, GEMM_SMEM);
    cudaFuncSetAttribute(attn_mma, cudaFuncAttributeMaxDynamicSharedMemorySize, ATTN_SMEM);

    const int nHid  = TT * HID;
    const int nWqkv = QKVD * HID;
    const int nWo   = HID * HID;
    const int nQkv  = TT * QKVD;

    split_f16<<<(nHid / 4 + 255) / 256, 256>>>(hidden, hid_hi, hid_lo, nHid / 4);
    conv_f16<<<(nWqkv / 4 + 255) / 256, 256>>>(wqkv, wqkv_h, nWqkv / 4);

    gemm_f16<<<dim3(TT / GBM, QKVD / GBN), 512, GEMM_SMEM>>>(
        hid_hi, hid_lo, wqkv_h, bqkv, qkv_ptr, TT, QKVD, HID);

    rope_kernel<<<dim3(10, TT), 256>>>(qkv_ptr, positions);

    // preconvert rope'd qkv to bf16 hi/lo (shared by all heads)
    split_bf<<<(nQkv / 4 + 255) / 256, 256>>>(qkv_ptr, qkv_hi, qkv_lo, nQkv / 4);

    attn_mma<<<dim3(TT / 128, NH), 256, ATTN_SMEM>>>(qkv_hi, qkv_lo, attn_hi, attn_lo, window);

    conv_f16<<<(nWo / 4 + 255) / 256, 256>>>(wo, wo_h, nWo / 4);

    gemm_f16<<<dim3(TT / GBM, HID / GBN), 512, GEMM_SMEM>>>(
        attn_hi, attn_lo, wo_h, bo, out, TT, HID, HID);
}

// round 16
// speedup vs baseline: 1.1851x; 1.0714x over previous
#include <cuda_runtime.h>
#include <cuda_bf16.h>
#include <cuda_fp16.h>
#include <math.h>
#include <stdint.h>

#define TT 2048
#define HID 4608
#define NH 36
#define NKV 4
#define HD 128
#define QKVD 5632
#define GROUP 9
#define ATT_SCALE 0.08838834764831843f
#define LOG2E 1.4426950408889634f

// ---------------- scratch ----------------
__device__ float g_qkv[TT * QKVD];
__device__ __half g_qkv_hi[TT * QKVD];
__device__ __half g_qkv_lo[TT * QKVD];
__device__ __half g_hid_hi[TT * HID];
__device__ __half g_hid_lo[TT * HID];
__device__ __half g_wqkv_h[QKVD * HID];
__device__ __half g_wo_h[HID * HID];
__device__ __half g_attn_hi[TT * HID];
__device__ __half g_attn_lo[TT * HID];

__device__ __forceinline__ uint32_t smem_u32(const void* p) {
    uint32_t a;
    asm("{ .reg .u64 t; cvta.to.shared.u64 t, %1; cvt.u32.u64 %0, t; }" : "=r"(a) : "l"(p));
    return a;
}
__device__ __forceinline__ float ex2(float x) {
    float r;
    asm("ex2.approx.f32 %0, %1;" : "=f"(r) : "f"(x));
    return r;
}
__device__ __forceinline__ void ldm_x4(uint32_t* r, uint32_t addr) {
    asm volatile("ldmatrix.sync.aligned.m8n8.x4.shared.b16 {%0,%1,%2,%3}, [%4];"
                 : "=r"(r[0]), "=r"(r[1]), "=r"(r[2]), "=r"(r[3]) : "r"(addr));
}
__device__ __forceinline__ void ldm_x4_t(uint32_t* r, uint32_t addr) {
    asm volatile("ldmatrix.sync.aligned.m8n8.x4.trans.shared.b16 {%0,%1,%2,%3}, [%4];"
                 : "=r"(r[0]), "=r"(r[1]), "=r"(r[2]), "=r"(r[3]) : "r"(addr));
}
// fp16 MMA, f32 acc (GEMMs + attention)
__device__ __forceinline__ void mma16816h(float* d, const uint32_t* a, uint32_t b0, uint32_t b1) {
    asm volatile(
        "mma.sync.aligned.m16n8k16.row.col.f32.f16.f16.f32 "
        "{%0,%1,%2,%3}, {%4,%5,%6,%7}, {%8,%9}, {%0,%1,%2,%3};"
        : "+f"(d[0]), "+f"(d[1]), "+f"(d[2]), "+f"(d[3])
        : "r"(a[0]), "r"(a[1]), "r"(a[2]), "r"(a[3]), "r"(b0), "r"(b1));
}
__device__ __forceinline__ uint32_t pack2h(__half a, __half b) {
    __half2 t(a, b);
    return *reinterpret_cast<uint32_t*>(&t);
}
__device__ __forceinline__ void split4h(float4 v, uint2& hi, uint2& lo) {
    __half h0 = __float2half(v.x), h1 = __float2half(v.y);
    __half h2 = __float2half(v.z), h3 = __float2half(v.w);
    __half l0 = __float2half(v.x - __half2float(h0));
    __half l1 = __float2half(v.y - __half2float(h1));
    __half l2 = __float2half(v.z - __half2float(h2));
    __half l3 = __float2half(v.w - __half2float(h3));
    hi.x = pack2h(h0, h1); hi.y = pack2h(h2, h3);
    lo.x = pack2h(l0, l1); lo.y = pack2h(l2, l3);
}

// ---------------------------------------------------------------------------
// fp32 -> fp16 hi/lo split (activations for GEMMs)
// ---------------------------------------------------------------------------
__global__ __launch_bounds__(256) void split_f16(const float* __restrict__ x,
                                                 __half* __restrict__ hi,
                                                 __half* __restrict__ lo,
                                                 int n4)
{
    int i = blockIdx.x * 256 + threadIdx.x;
    if (i >= n4) return;
    float4 v = ((const float4*)x)[i];
    uint2 H, L;
    split4h(v, H, L);
    ((uint2*)hi)[i] = H;
    ((uint2*)lo)[i] = L;
}

// fp32 -> fp16 plain convert (weights)
__global__ __launch_bounds__(256) void conv_f16(const float* __restrict__ x,
                                                __half* __restrict__ y,
                                                int n4)
{
    int i = blockIdx.x * 256 + threadIdx.x;
    if (i >= n4) return;
    float4 v = ((const float4*)x)[i];
    uint2 H;
    H.x = pack2h(__float2half(v.x), __float2half(v.y));
    H.y = pack2h(__float2half(v.z), __float2half(v.w));
    ((uint2*)y)[i] = H;
}

// ---------------------------------------------------------------------------
// Fused NeoX RoPE + fp16 hi/lo split of qkv.
// grid (6, TT), 512 threads. Blocks 0..4: rope+split on q/k heads (8 heads/blk).
// Block 5: v region, split only.
// ---------------------------------------------------------------------------
__global__ __launch_bounds__(512) void rope_split(const float* __restrict__ qkv,
                                                  const int* __restrict__ positions,
                                                  __half* __restrict__ hi,
                                                  __half* __restrict__ lo)
{
    const int t = blockIdx.y;
    const int bx = blockIdx.x;
    const int tid = threadIdx.x;

    if (bx < 5) {
        const int hh = bx * 8 + (tid >> 6);   // 0..39 (q heads 0..35, k heads 36..39)
        const int d = tid & 63;
        const size_t base = (size_t)t * QKVD + hh * HD;
        const float x1 = qkv[base + d];
        const float x2 = qkv[base + d + 64];
        const float pos = (float)positions[t];
        const float inv_freq = expf(-11.512925464970229f * ((float)d / 64.0f));
        const float ang = pos * inv_freq;
        float s, c;
        sincosf(ang, &s, &c);
        const float y1 = x1 * c - x2 * s;
        const float y2 = x2 * c + x1 * s;
        const __half h1 = __float2half(y1), h2 = __float2half(y2);
        hi[base + d]      = h1;
        hi[base + d + 64] = h2;
        lo[base + d]      = __float2half(y1 - __half2float(h1));
        lo[base + d + 64] = __float2half(y2 - __half2float(h2));
    } else {
        const size_t base = (size_t)t * QKVD + 5120 + tid;   // v region (512 floats)
        const float v = qkv[base];
        const __half h = __float2half(v);
        hi[base] = h;
        lo[base] = __float2half(v - __half2float(h));
    }
}

// ---------------------------------------------------------------------------
// fp16x2 GEMM (round-10 proven: BK=64, 3-stage, all f32 acc, 512 threads)
// ---------------------------------------------------------------------------
#define GBM 128
#define GBN 128
#define GBK 64
#define ROWB 144
#define TILE_B (128 * ROWB)
#define STAGE_B (3 * TILE_B)
#define NSTG 3
#define GEMM_SMEM (NSTG * STAGE_B)

__global__ __launch_bounds__(512, 1) void gemm_f16(
    const __half* __restrict__ Ahi, const __half* __restrict__ Alo,
    const __half* __restrict__ Bh,
    const float* __restrict__ bias, float* __restrict__ C,
    int M, int N, int K)
{
    extern __shared__ char smem[];
    const uint32_t sb = smem_u32(smem);
    const int tid = threadIdx.x, wid = tid >> 5, lane = tid & 31;
    const int warp_m = wid & 3;
    const int warp_n = wid >> 2;
    const int bm = blockIdx.x * GBM, bn = blockIdx.y * GBN;

    float acc[2][4][4];
#pragma unroll
    for (int i = 0; i < 2; i++)
#pragma unroll
        for (int j = 0; j < 4; j++)
#pragma unroll
            for (int q = 0; q < 4; q++) acc[i][j][q] = 0.0f;

    auto load_stage = [&](int stg, int k0) {
        uint32_t base = sb + stg * STAGE_B;
#pragma unroll
        for (int i = 0; i < 6; i++) {
            int c = tid + i * 512;
            int tile = c >> 10;
            int idx = c & 1023;
            int row = idx >> 3, ch = idx & 7;
            const __half* g;
            int grow;
            if (tile == 0) { g = Ahi; grow = bm + row; }
            else if (tile == 1) { g = Alo; grow = bm + row; }
            else { g = Bh; grow = bn + row; }
            const char* src = (const char*)(g + (size_t)grow * K + k0) + ch * 16;
            uint32_t dst = base + tile * TILE_B + row * ROWB + ch * 16;
            asm volatile("cp.async.cg.shared.global [%0], [%1], 16;" :: "r"(dst), "l"(src));
        }
        asm volatile("cp.async.commit_group;" ::: "memory");
    };

    const int NKB = K / GBK;
    load_stage(0, 0);
    load_stage(1, GBK);

    const int a_row = (lane & 15);
    const int a_kh = lane >> 4;
    const int b_nrow = (lane & 7) + ((lane >> 4) & 1) * 8;
    const int b_kh = (lane >> 3) & 1;

    for (int kb = 0; kb < NKB; kb++) {
        const int cur = kb % NSTG;
        if (kb + 1 < NKB) { asm volatile("cp.async.wait_group 1;" ::: "memory"); }
        else              { asm volatile("cp.async.wait_group 0;" ::: "memory"); }
        __syncthreads();

        if (kb + 2 < NKB) load_stage((kb + 2) % NSTG, (kb + 2) * GBK);

        const uint32_t stage = sb + cur * STAGE_B;
        const uint32_t Ah = stage;
        const uint32_t Al = stage + TILE_B;
        const uint32_t Bt = stage + 2 * TILE_B;

#pragma unroll
        for (int ks = 0; ks < 4; ks++) {
            uint32_t ah[2][4], al[2][4];
#pragma unroll
            for (int mf = 0; mf < 2; mf++) {
                uint32_t off = (warp_m * 32 + mf * 16 + a_row) * ROWB + ks * 32 + a_kh * 16;
                ldm_x4(ah[mf], Ah + off);
                ldm_x4(al[mf], Al + off);
            }
            uint32_t bh[2][4];
#pragma unroll
            for (int p = 0; p < 2; p++) {
                uint32_t off = (warp_n * 32 + p * 16 + b_nrow) * ROWB + ks * 32 + b_kh * 16;
                ldm_x4(bh[p], Bt + off);
            }
#pragma unroll
            for (int mf = 0; mf < 2; mf++)
#pragma unroll
                for (int nf = 0; nf < 4; nf++) {
                    const int p = nf >> 1, o = (nf & 1) * 2;
                    mma16816h(acc[mf][nf], ah[mf], bh[p][o], bh[p][o + 1]);  // Ah*B
                }
#pragma unroll
            for (int mf = 0; mf < 2; mf++)
#pragma unroll
                for (int nf = 0; nf < 4; nf++) {
                    const int p = nf >> 1, o = (nf & 1) * 2;
                    mma16816h(acc[mf][nf], al[mf], bh[p][o], bh[p][o + 1]);  // Al*B
                }
        }
    }

    const int qr = lane >> 2, qc = (lane & 3) * 2;
#pragma unroll
    for (int mf = 0; mf < 2; mf++) {
        int row0 = bm + warp_m * 32 + mf * 16 + qr;
#pragma unroll
        for (int nf = 0; nf < 4; nf++) {
            int col = bn + warp_n * 32 + nf * 8 + qc;
            float2 bv = *(const float2*)(bias + col);
            float2 v0 = { acc[mf][nf][0] + bv.x, acc[mf][nf][1] + bv.y };
            float2 v1 = { acc[mf][nf][2] + bv.x, acc[mf][nf][3] + bv.y };
            *(float2*)(C + (size_t)row0 * N + col) = v0;
            *(float2*)(C + (size_t)(row0 + 8) * N + col) = v1;
        }
    }
}

// ---------------------------------------------------------------------------
// Windowed causal flash attention, fp16x2: Q hi/lo, K single, V single, P hi/lo.
// 2-stage cp.async KV ring. Epilogue writes fp16 hi/lo.
// ---------------------------------------------------------------------------
#define AROWB 272
#define AQ_B (128 * AROWB)         // 34816
#define AK_B (64 * AROWB)          // 17408
#define KVSTG (2 * AK_B)           // 34816: K, V (single fp16 each)
#define ATTN_SMEM (2 * AQ_B + 2 * KVSTG)  // 139264

__global__ __launch_bounds__(256, 1) void attn_mma(
    const __half* __restrict__ qhi,
    const __half* __restrict__ qlo,
    __half* __restrict__ outHi,
    __half* __restrict__ outLo,
    const int* __restrict__ winp)
{
    extern __shared__ char smem[];
    const uint32_t sb = smem_u32(smem);
    const uint32_t Qhi = sb, Qlo = sb + AQ_B;
    const uint32_t KV0 = sb + 2 * AQ_B;

    const int tid = threadIdx.x, w = tid >> 5, lane = tid & 31;
    const int h = blockIdx.y, qt0 = blockIdx.x * 128;
    const int kvh = h / GROUP;
    const int window = *winp;
    const int g = lane >> 2, qc2 = (lane & 3) * 2;

    const size_t qOff = (size_t)h * HD;
    const size_t kOff = (size_t)NH * HD + (size_t)kvh * HD;
    const size_t vOff = kOff + (size_t)NKV * HD;

    int sBegin = qt0 - window + 1;
    if (sBegin < 0) sBegin = 0;
    sBegin &= ~63;
    const int nIter = (qt0 + 128 - sBegin) / 64;

    // KV stage loader: 2 tiles x 64 rows x 16 chunks(16B) = 2048, 8/thread
    auto load_kv = [&](int stg, int s0) {
        uint32_t base = KV0 + stg * KVSTG;
#pragma unroll
        for (int i = 0; i < 8; i++) {
            int c = tid + i * 256;
            int t_ = c >> 10;           // 0:K 1:V
            int idx = c & 1023;
            int row = idx >> 4, ch = idx & 15;
            size_t off = t_ ? vOff : kOff;
            const char* src = (const char*)(qhi + (size_t)(s0 + row) * QKVD + off) + ch * 16;
            uint32_t dst = base + t_ * AK_B + row * AROWB + ch * 16;
            asm volatile("cp.async.cg.shared.global [%0], [%1], 16;" :: "r"(dst), "l"(src));
        }
        asm volatile("cp.async.commit_group;" ::: "memory");
    };

    // Q load (2 tiles x 128 rows x 16 chunks = 4096, 16/thread); joins group 0
#pragma unroll
    for (int i = 0; i < 16; i++) {
        int c = tid + i * 256;
        int t_ = c >> 11;               // 0:hi 1:lo
        int idx = c & 2047;
        int row = idx >> 4, ch = idx & 15;
        const __half* gp = t_ ? qlo : qhi;
        const char* src = (const char*)(gp + (size_t)(qt0 + row) * QKVD + qOff) + ch * 16;
        uint32_t dst = (t_ ? Qlo : Qhi) + row * AROWB + ch * 16;
        asm volatile("cp.async.cg.shared.global [%0], [%1], 16;" :: "r"(dst), "l"(src));
    }
    load_kv(0, sBegin);                 // commits group 0 (Q + KV stage 0)
    if (nIter > 1) load_kv(1, sBegin + 64);

    float m0 = -1e30f, m1 = -1e30f, l0 = 0.0f, l1 = 0.0f;
    float O[16][4];
#pragma unroll
    for (int i = 0; i < 16; i++)
#pragma unroll
        for (int j = 0; j < 4; j++) O[i][j] = 0.0f;

    const int a_row = (lane & 15);
    const int a_kh = lane >> 4;
    const int b_nrow = (lane & 7) + ((lane >> 4) & 1) * 8;
    const int b_kh = (lane >> 3) & 1;
    const int vkr = (lane & 7) + ((lane >> 3) & 1) * 8;
    const int vnc = ((lane >> 4) & 1) * 8;

    const float sc = ATT_SCALE * LOG2E;
    const int qrow0 = qt0 + w * 16 + g;
    const int qrow1 = qrow0 + 8;

    int it = 0;
    for (int s0 = sBegin; it < nIter; s0 += 64, it++) {
        if (it + 1 < nIter) { asm volatile("cp.async.wait_group 1;" ::: "memory"); }
        else                { asm volatile("cp.async.wait_group 0;" ::: "memory"); }
        __syncthreads();

        const int cur = it & 1;
        const uint32_t Kt = KV0 + cur * KVSTG;
        const uint32_t Vt = Kt + AK_B;

        // ---- S = (Qh + Ql) K^T ----
        float S[8][4];
#pragma unroll
        for (int i = 0; i < 8; i++)
#pragma unroll
            for (int j = 0; j < 4; j++) S[i][j] = 0.0f;

#pragma unroll
        for (int kf = 0; kf < 8; kf++) {
            uint32_t ah[4], al[4];
            uint32_t aoff = (w * 16 + a_row) * AROWB + kf * 32 + a_kh * 16;
            ldm_x4(ah, Qhi + aoff);
            ldm_x4(al, Qlo + aoff);
#pragma unroll
            for (int nt = 0; nt < 4; nt++) {
                uint32_t bh[4];
                uint32_t boff = (nt * 16 + b_nrow) * AROWB + kf * 32 + b_kh * 16;
                ldm_x4(bh, Kt + boff);
                mma16816h(S[2 * nt],     ah, bh[0], bh[1]);
                mma16816h(S[2 * nt + 1], ah, bh[2], bh[3]);
                mma16816h(S[2 * nt],     al, bh[0], bh[1]);
                mma16816h(S[2 * nt + 1], al, bh[2], bh[3]);
            }
        }

        // ---- scale + mask (log2 domain) ----
#pragma unroll
        for (int nf = 0; nf < 8; nf++) {
            int c0 = s0 + nf * 8 + qc2;
#pragma unroll
            for (int c = 0; c < 4; c++) {
                int col = c0 + (c & 1);
                int row = (c < 2) ? qrow0 : qrow1;
                bool ok = (col <= row) && (col > row - window);
                S[nf][c] = ok ? S[nf][c] * sc : -1e30f;
            }
        }

        // ---- online softmax ----
        float mx0 = -1e30f, mx1 = -1e30f;
#pragma unroll
        for (int nf = 0; nf < 8; nf++) {
            mx0 = fmaxf(mx0, fmaxf(S[nf][0], S[nf][1]));
            mx1 = fmaxf(mx1, fmaxf(S[nf][2], S[nf][3]));
        }
        mx0 = fmaxf(mx0, __shfl_xor_sync(0xffffffffu, mx0, 1));
        mx0 = fmaxf(mx0, __shfl_xor_sync(0xffffffffu, mx0, 2));
        mx1 = fmaxf(mx1, __shfl_xor_sync(0xffffffffu, mx1, 1));
        mx1 = fmaxf(mx1, __shfl_xor_sync(0xffffffffu, mx1, 2));

        float mn0 = fmaxf(m0, mx0), mn1 = fmaxf(m1, mx1);
        float corr0 = ex2(m0 - mn0), corr1 = ex2(m1 - mn1);
        m0 = mn0; m1 = mn1;

        uint32_t Phi[4][4], Plo[4][4];
        float rs0 = 0.0f, rs1 = 0.0f;
#pragma unroll
        for (int nf = 0; nf < 8; nf++) {
            float p0 = ex2(S[nf][0] - mn0);
            float p1 = ex2(S[nf][1] - mn0);
            float p2 = ex2(S[nf][2] - mn1);
            float p3 = ex2(S[nf][3] - mn1);
            rs0 += p0 + p1;
            rs1 += p2 + p3;
            __half h0 = __float2half(p0), h1 = __float2half(p1);
            __half h2 = __float2half(p2), h3 = __float2half(p3);
            __half e0 = __float2half(p0 - __half2float(h0));
            __half e1 = __float2half(p1 - __half2float(h1));
            __half e2 = __float2half(p2 - __half2float(h2));
            __half e3 = __float2half(p3 - __half2float(h3));
            const int kf = nf >> 1;
            if ((nf & 1) == 0) {
                Phi[kf][0] = pack2h(h0, h1); Phi[kf][1] = pack2h(h2, h3);
                Plo[kf][0] = pack2h(e0, e1); Plo[kf][1] = pack2h(e2, e3);
            } else {
                Phi[kf][2] = pack2h(h0, h1); Phi[kf][3] = pack2h(h2, h3);
                Plo[kf][2] = pack2h(e0, e1); Plo[kf][3] = pack2h(e2, e3);
            }
        }
        rs0 += __shfl_xor_sync(0xffffffffu, rs0, 1);
        rs0 += __shfl_xor_sync(0xffffffffu, rs0, 2);
        rs1 += __shfl_xor_sync(0xffffffffu, rs1, 1);
        rs1 += __shfl_xor_sync(0xffffffffu, rs1, 2);

        l0 = l0 * corr0 + rs0;
        l1 = l1 * corr1 + rs1;
#pragma unroll
        for (int nf = 0; nf < 16; nf++) {
            O[nf][0] *= corr0; O[nf][1] *= corr0;
            O[nf][2] *= corr1; O[nf][3] *= corr1;
        }

        // ---- O += (Ph + Pl) V ----
#pragma unroll
        for (int kf = 0; kf < 4; kf++) {
#pragma unroll
            for (int nt = 0; nt < 8; nt++) {
                uint32_t vh[4];
                uint32_t voff = (kf * 16 + vkr) * AROWB + (nt * 16 + vnc) * 2;
                ldm_x4_t(vh, Vt + voff);
                mma16816h(O[2 * nt],     Phi[kf], vh[0], vh[1]);
                mma16816h(O[2 * nt + 1], Phi[kf], vh[2], vh[3]);
                mma16816h(O[2 * nt],     Plo[kf], vh[0], vh[1]);
                mma16816h(O[2 * nt + 1], Plo[kf], vh[2], vh[3]);
            }
        }

        __syncthreads();   // all warps done with stage 'cur' before refill
        if (it + 2 < nIter) load_kv(cur, s0 + 128);
    }

    // ---- epilogue: normalize, split to fp16 hi/lo, store ----
    const float inv0 = 1.0f / l0, inv1 = 1.0f / l1;
#pragma unroll
    for (int nf = 0; nf < 16; nf++) {
        int col = nf * 8 + qc2;
        size_t base0 = (size_t)qrow0 * HID + h * HD + col;
        size_t base1 = (size_t)qrow1 * HID + h * HD + col;
        float x0 = O[nf][0] * inv0, x1 = O[nf][1] * inv0;
        float x2 = O[nf][2] * inv1, x3 = O[nf][3] * inv1;
        __half h0 = __float2half(x0), h1 = __float2half(x1);
        __half h2 = __float2half(x2), h3 = __float2half(x3);
        *(uint32_t*)(outHi + base0) = pack2h(h0, h1);
        *(uint32_t*)(outHi + base1) = pack2h(h2, h3);
        __half e0 = __float2half(x0 - __half2float(h0));
        __half e1 = __float2half(x1 - __half2float(h1));
        __half e2 = __float2half(x2 - __half2float(h2));
        __half e3 = __float2half(x3 - __half2float(h3));
        *(uint32_t*)(outLo + base0) = pack2h(e0, e1);
        *(uint32_t*)(outLo + base1) = pack2h(e2, e3);
    }
}

// ---------------------------------------------------------------------------
extern "C" void kernel_launch(void* const* d_in, const int* in_sizes, int n_in,
                              void* d_out, int out_size)
{
    const int*   positions = (const int*)d_in[0];
    const float* hidden    = (const float*)d_in[1];
    const float* wqkv      = (const float*)d_in[2];
    const float* bqkv      = (const float*)d_in[3];
    const float* wo        = (const float*)d_in[4];
    const float* bo        = (const float*)d_in[5];
    const int*   window    = (const int*)d_in[6];
    float* out = (float*)d_out;

    float* qkv_ptr;
    __half *qkv_hi, *qkv_lo;
    __half *hid_hi, *hid_lo, *wqkv_h, *wo_h, *attn_hi, *attn_lo;
    cudaGetSymbolAddress((void**)&qkv_ptr,  g_qkv);
    cudaGetSymbolAddress((void**)&qkv_hi,   g_qkv_hi);
    cudaGetSymbolAddress((void**)&qkv_lo,   g_qkv_lo);
    cudaGetSymbolAddress((void**)&hid_hi,   g_hid_hi);
    cudaGetSymbolAddress((void**)&hid_lo,   g_hid_lo);
    cudaGetSymbolAddress((void**)&wqkv_h,   g_wqkv_h);
    cudaGetSymbolAddress((void**)&wo_h,     g_wo_h);
    cudaGetSymbolAddress((void**)&attn_hi,  g_attn_hi);
    cudaGetSymbolAddress((void**)&attn_lo,  g_attn_lo);

    cudaFuncSetAttribute(gemm_f16, cudaFuncAttributeMaxDynamicSharedMemorySize, GEMM_SMEM);
    cudaFuncSetAttribute(attn_mma, cudaFuncAttributeMaxDynamicSharedMemorySize, ATTN_SMEM);

    const int nHid  = TT * HID;
    const int nWqkv = QKVD * HID;
    const int nWo   = HID * HID;

    split_f16<<<(nHid / 4 + 255) / 256, 256>>>(hidden, hid_hi, hid_lo, nHid / 4);
    conv_f16<<<(nWqkv / 4 + 255) / 256, 256>>>(wqkv, wqkv_h, nWqkv / 4);

    gemm_f16<<<dim3(TT / GBM, QKVD / GBN), 512, GEMM_SMEM>>>(
        hid_hi, hid_lo, wqkv_h, bqkv, qkv_ptr, TT, QKVD, HID);

    // fused rope + fp16 hi/lo split of qkv
    rope_split<<<dim3(6, TT), 512>>>(qkv_ptr, positions, qkv_hi, qkv_lo);

    attn_mma<<<dim3(TT / 128, NH), 256, ATTN_SMEM>>>(qkv_hi, qkv_lo, attn_hi, attn_lo, window);

    conv_f16<<<(nWo / 4 + 255) / 256, 256>>>(wo, wo_h, nWo / 4);

    gemm_f16<<<dim3(TT / GBM, HID / GBN), 512, GEMM_SMEM>>>(
        attn_hi, attn_lo, wo_h, bo, out, TT, HID, HID);
}

// round 17
// speedup vs baseline: 1.2616x; 1.0646x over previous
#include <cuda_runtime.h>
#include <cuda_bf16.h>
#include <cuda_fp16.h>
#include <math.h>
#include <stdint.h>

#define TT 2048
#define HID 4608
#define NH 36
#define NKV 4
#define HD 128
#define QKVD 5632
#define GROUP 9
#define ATT_SCALE 0.08838834764831843f
#define LOG2E 1.4426950408889634f

// ---------------- scratch ----------------
__device__ float g_qkv[TT * QKVD];
__device__ __half g_qkv_hi[TT * QKVD];
__device__ __half g_qkv_lo[TT * QKVD];
__device__ __half g_hid_hi[TT * HID];
__device__ __half g_hid_lo[TT * HID];
__device__ __half g_wqkv_h[QKVD * HID];
__device__ __half g_wo_h[HID * HID];
__device__ __half g_attn_hi[TT * HID];
__device__ __half g_attn_lo[TT * HID];

__device__ __forceinline__ uint32_t smem_u32(const void* p) {
    uint32_t a;
    asm("{ .reg .u64 t; cvta.to.shared.u64 t, %1; cvt.u32.u64 %0, t; }" : "=r"(a) : "l"(p));
    return a;
}
__device__ __forceinline__ float ex2(float x) {
    float r;
    asm("ex2.approx.f32 %0, %1;" : "=f"(r) : "f"(x));
    return r;
}
__device__ __forceinline__ void ldm_x4(uint32_t* r, uint32_t addr) {
    asm volatile("ldmatrix.sync.aligned.m8n8.x4.shared.b16 {%0,%1,%2,%3}, [%4];"
                 : "=r"(r[0]), "=r"(r[1]), "=r"(r[2]), "=r"(r[3]) : "r"(addr));
}
__device__ __forceinline__ void ldm_x4_t(uint32_t* r, uint32_t addr) {
    asm volatile("ldmatrix.sync.aligned.m8n8.x4.trans.shared.b16 {%0,%1,%2,%3}, [%4];"
                 : "=r"(r[0]), "=r"(r[1]), "=r"(r[2]), "=r"(r[3]) : "r"(addr));
}
// fp16 MMA, f32 acc
__device__ __forceinline__ void mma16816h(float* d, const uint32_t* a, uint32_t b0, uint32_t b1) {
    asm volatile(
        "mma.sync.aligned.m16n8k16.row.col.f32.f16.f16.f32 "
        "{%0,%1,%2,%3}, {%4,%5,%6,%7}, {%8,%9}, {%0,%1,%2,%3};"
        : "+f"(d[0]), "+f"(d[1]), "+f"(d[2]), "+f"(d[3])
        : "r"(a[0]), "r"(a[1]), "r"(a[2]), "r"(a[3]), "r"(b0), "r"(b1));
}
__device__ __forceinline__ uint32_t pack2h(__half a, __half b) {
    __half2 t(a, b);
    return *reinterpret_cast<uint32_t*>(&t);
}
__device__ __forceinline__ void split4h(float4 v, uint2& hi, uint2& lo) {
    __half h0 = __float2half(v.x), h1 = __float2half(v.y);
    __half h2 = __float2half(v.z), h3 = __float2half(v.w);
    __half l0 = __float2half(v.x - __half2float(h0));
    __half l1 = __float2half(v.y - __half2float(h1));
    __half l2 = __float2half(v.z - __half2float(h2));
    __half l3 = __float2half(v.w - __half2float(h3));
    hi.x = pack2h(h0, h1); hi.y = pack2h(h2, h3);
    lo.x = pack2h(l0, l1); lo.y = pack2h(l2, l3);
}

// ---------------------------------------------------------------------------
__global__ __launch_bounds__(256) void split_f16(const float* __restrict__ x,
                                                 __half* __restrict__ hi,
                                                 __half* __restrict__ lo,
                                                 int n4)
{
    int i = blockIdx.x * 256 + threadIdx.x;
    if (i >= n4) return;
    float4 v = ((const float4*)x)[i];
    uint2 H, L;
    split4h(v, H, L);
    ((uint2*)hi)[i] = H;
    ((uint2*)lo)[i] = L;
}

__global__ __launch_bounds__(256) void conv_f16(const float* __restrict__ x,
                                                __half* __restrict__ y,
                                                int n4)
{
    int i = blockIdx.x * 256 + threadIdx.x;
    if (i >= n4) return;
    float4 v = ((const float4*)x)[i];
    uint2 H;
    H.x = pack2h(__float2half(v.x), __float2half(v.y));
    H.y = pack2h(__float2half(v.z), __float2half(v.w));
    ((uint2*)y)[i] = H;
}

// ---------------------------------------------------------------------------
// Fused NeoX RoPE + fp16 hi/lo split of qkv.
// ---------------------------------------------------------------------------
__global__ __launch_bounds__(512) void rope_split(const float* __restrict__ qkv,
                                                  const int* __restrict__ positions,
                                                  __half* __restrict__ hi,
                                                  __half* __restrict__ lo)
{
    const int t = blockIdx.y;
    const int bx = blockIdx.x;
    const int tid = threadIdx.x;

    if (bx < 5) {
        const int hh = bx * 8 + (tid >> 6);
        const int d = tid & 63;
        const size_t base = (size_t)t * QKVD + hh * HD;
        const float x1 = qkv[base + d];
        const float x2 = qkv[base + d + 64];
        const float pos = (float)positions[t];
        const float inv_freq = expf(-11.512925464970229f * ((float)d / 64.0f));
        const float ang = pos * inv_freq;
        float s, c;
        sincosf(ang, &s, &c);
        const float y1 = x1 * c - x2 * s;
        const float y2 = x2 * c + x1 * s;
        const __half h1 = __float2half(y1), h2 = __float2half(y2);
        hi[base + d]      = h1;
        hi[base + d + 64] = h2;
        lo[base + d]      = __float2half(y1 - __half2float(h1));
        lo[base + d + 64] = __float2half(y2 - __half2float(h2));
    } else {
        const size_t base = (size_t)t * QKVD + 5120 + tid;
        const float v = qkv[base];
        const __half h = __float2half(v);
        hi[base] = h;
        lo[base] = __float2half(v - __half2float(h));
    }
}

// ---------------------------------------------------------------------------
// fp16x2 GEMM, occupancy-2 variant: 256 threads (8 warps 4x2, 32x64/warp),
// BK=64, 2 stages (108 KB smem -> 2 CTAs/SM). All f32 accumulate.
// ---------------------------------------------------------------------------
#define GBM 128
#define GBN 128
#define GBK 64
#define ROWB 144
#define TILE_B (128 * ROWB)         // 18432
#define STAGE_B (3 * TILE_B)        // 55296
#define NSTG 2
#define GEMM_SMEM (NSTG * STAGE_B)  // 110592

__global__ __launch_bounds__(256, 2) void gemm_f16(
    const __half* __restrict__ Ahi, const __half* __restrict__ Alo,
    const __half* __restrict__ Bh,
    const float* __restrict__ bias, float* __restrict__ C,
    int M, int N, int K)
{
    extern __shared__ char smem[];
    const uint32_t sb = smem_u32(smem);
    const int tid = threadIdx.x, wid = tid >> 5, lane = tid & 31;
    const int warp_m = wid & 3;          // 4 warps over M (32 rows)
    const int warp_n = wid >> 2;         // 2 warps over N (64 cols)
    const int bm = blockIdx.x * GBM, bn = blockIdx.y * GBN;

    float acc[2][8][4];
#pragma unroll
    for (int i = 0; i < 2; i++)
#pragma unroll
        for (int j = 0; j < 8; j++)
#pragma unroll
            for (int q = 0; q < 4; q++) acc[i][j][q] = 0.0f;

    // stage loader: 3 tiles x 128 rows x 8 chunks(16B) = 3072 chunks, 12/thread
    auto load_stage = [&](int stg, int k0) {
        uint32_t base = sb + stg * STAGE_B;
#pragma unroll
        for (int i = 0; i < 12; i++) {
            int c = tid + i * 256;
            int tile = c >> 10;          // 0:Ahi 1:Alo 2:Bh
            int idx = c & 1023;
            int row = idx >> 3, ch = idx & 7;
            const __half* g;
            int grow;
            if (tile == 0) { g = Ahi; grow = bm + row; }
            else if (tile == 1) { g = Alo; grow = bm + row; }
            else { g = Bh; grow = bn + row; }
            const char* src = (const char*)(g + (size_t)grow * K + k0) + ch * 16;
            uint32_t dst = base + tile * TILE_B + row * ROWB + ch * 16;
            asm volatile("cp.async.cg.shared.global [%0], [%1], 16;" :: "r"(dst), "l"(src));
        }
        asm volatile("cp.async.commit_group;" ::: "memory");
    };

    const int NKB = K / GBK;
    load_stage(0, 0);
    load_stage(1, GBK);

    const int a_row = (lane & 15);
    const int a_kh = lane >> 4;
    const int b_nrow = (lane & 7) + ((lane >> 4) & 1) * 8;
    const int b_kh = (lane >> 3) & 1;

    for (int kb = 0; kb < NKB; kb++) {
        const int cur = kb & 1;
        if (kb + 1 < NKB) { asm volatile("cp.async.wait_group 1;" ::: "memory"); }
        else              { asm volatile("cp.async.wait_group 0;" ::: "memory"); }
        __syncthreads();

        const uint32_t stage = sb + cur * STAGE_B;
        const uint32_t Ah = stage;
        const uint32_t Al = stage + TILE_B;
        const uint32_t Bt = stage + 2 * TILE_B;

#pragma unroll
        for (int ks = 0; ks < 4; ks++) {
            uint32_t ah[2][4], al[2][4];
#pragma unroll
            for (int mf = 0; mf < 2; mf++) {
                uint32_t off = (warp_m * 32 + mf * 16 + a_row) * ROWB + ks * 32 + a_kh * 16;
                ldm_x4(ah[mf], Ah + off);
                ldm_x4(al[mf], Al + off);
            }
            uint32_t bh[4][4];
#pragma unroll
            for (int p = 0; p < 4; p++) {
                uint32_t off = (warp_n * 64 + p * 16 + b_nrow) * ROWB + ks * 32 + b_kh * 16;
                ldm_x4(bh[p], Bt + off);
            }
#pragma unroll
            for (int mf = 0; mf < 2; mf++)
#pragma unroll
                for (int nf = 0; nf < 8; nf++) {
                    const int p = nf >> 1, o = (nf & 1) * 2;
                    mma16816h(acc[mf][nf], ah[mf], bh[p][o], bh[p][o + 1]);  // Ah*B
                }
#pragma unroll
            for (int mf = 0; mf < 2; mf++)
#pragma unroll
                for (int nf = 0; nf < 8; nf++) {
                    const int p = nf >> 1, o = (nf & 1) * 2;
                    mma16816h(acc[mf][nf], al[mf], bh[p][o], bh[p][o + 1]);  // Al*B
                }
        }

        __syncthreads();
        if (kb + 2 < NKB) load_stage(cur, (kb + 2) * GBK);
    }

    const int qr = lane >> 2, qc = (lane & 3) * 2;
#pragma unroll
    for (int mf = 0; mf < 2; mf++) {
        int row0 = bm + warp_m * 32 + mf * 16 + qr;
#pragma unroll
        for (int nf = 0; nf < 8; nf++) {
            int col = bn + warp_n * 64 + nf * 8 + qc;
            float2 bv = *(const float2*)(bias + col);
            float2 v0 = { acc[mf][nf][0] + bv.x, acc[mf][nf][1] + bv.y };
            float2 v1 = { acc[mf][nf][2] + bv.x, acc[mf][nf][3] + bv.y };
            *(float2*)(C + (size_t)row0 * N + col) = v0;
            *(float2*)(C + (size_t)(row0 + 8) * N + col) = v1;
        }
    }
}

// ---------------------------------------------------------------------------
// Windowed causal flash attention, fp16x2 (round-16 proven).
// ---------------------------------------------------------------------------
#define AROWB 272
#define AQ_B (128 * AROWB)
#define AK_B (64 * AROWB)
#define KVSTG (2 * AK_B)
#define ATTN_SMEM (2 * AQ_B + 2 * KVSTG)  // 139264

__global__ __launch_bounds__(256, 1) void attn_mma(
    const __half* __restrict__ qhi,
    const __half* __restrict__ qlo,
    __half* __restrict__ outHi,
    __half* __restrict__ outLo,
    const int* __restrict__ winp)
{
    extern __shared__ char smem[];
    const uint32_t sb = smem_u32(smem);
    const uint32_t Qhi = sb, Qlo = sb + AQ_B;
    const uint32_t KV0 = sb + 2 * AQ_B;

    const int tid = threadIdx.x, w = tid >> 5, lane = tid & 31;
    const int h = blockIdx.y, qt0 = blockIdx.x * 128;
    const int kvh = h / GROUP;
    const int window = *winp;
    const int g = lane >> 2, qc2 = (lane & 3) * 2;

    const size_t qOff = (size_t)h * HD;
    const size_t kOff = (size_t)NH * HD + (size_t)kvh * HD;
    const size_t vOff = kOff + (size_t)NKV * HD;

    int sBegin = qt0 - window + 1;
    if (sBegin < 0) sBegin = 0;
    sBegin &= ~63;
    const int nIter = (qt0 + 128 - sBegin) / 64;

    auto load_kv = [&](int stg, int s0) {
        uint32_t base = KV0 + stg * KVSTG;
#pragma unroll
        for (int i = 0; i < 8; i++) {
            int c = tid + i * 256;
            int t_ = c >> 10;
            int idx = c & 1023;
            int row = idx >> 4, ch = idx & 15;
            size_t off = t_ ? vOff : kOff;
            const char* src = (const char*)(qhi + (size_t)(s0 + row) * QKVD + off) + ch * 16;
            uint32_t dst = base + t_ * AK_B + row * AROWB + ch * 16;
            asm volatile("cp.async.cg.shared.global [%0], [%1], 16;" :: "r"(dst), "l"(src));
        }
        asm volatile("cp.async.commit_group;" ::: "memory");
    };

#pragma unroll
    for (int i = 0; i < 16; i++) {
        int c = tid + i * 256;
        int t_ = c >> 11;
        int idx = c & 2047;
        int row = idx >> 4, ch = idx & 15;
        const __half* gp = t_ ? qlo : qhi;
        const char* src = (const char*)(gp + (size_t)(qt0 + row) * QKVD + qOff) + ch * 16;
        uint32_t dst = (t_ ? Qlo : Qhi) + row * AROWB + ch * 16;
        asm volatile("cp.async.cg.shared.global [%0], [%1], 16;" :: "r"(dst), "l"(src));
    }
    load_kv(0, sBegin);
    if (nIter > 1) load_kv(1, sBegin + 64);

    float m0 = -1e30f, m1 = -1e30f, l0 = 0.0f, l1 = 0.0f;
    float O[16][4];
#pragma unroll
    for (int i = 0; i < 16; i++)
#pragma unroll
        for (int j = 0; j < 4; j++) O[i][j] = 0.0f;

    const int a_row = (lane & 15);
    const int a_kh = lane >> 4;
    const int b_nrow = (lane & 7) + ((lane >> 4) & 1) * 8;
    const int b_kh = (lane >> 3) & 1;
    const int vkr = (lane & 7) + ((lane >> 3) & 1) * 8;
    const int vnc = ((lane >> 4) & 1) * 8;

    const float sc = ATT_SCALE * LOG2E;
    const int qrow0 = qt0 + w * 16 + g;
    const int qrow1 = qrow0 + 8;

    int it = 0;
    for (int s0 = sBegin; it < nIter; s0 += 64, it++) {
        if (it + 1 < nIter) { asm volatile("cp.async.wait_group 1;" ::: "memory"); }
        else                { asm volatile("cp.async.wait_group 0;" ::: "memory"); }
        __syncthreads();

        const int cur = it & 1;
        const uint32_t Kt = KV0 + cur * KVSTG;
        const uint32_t Vt = Kt + AK_B;

        float S[8][4];
#pragma unroll
        for (int i = 0; i < 8; i++)
#pragma unroll
            for (int j = 0; j < 4; j++) S[i][j] = 0.0f;

#pragma unroll
        for (int kf = 0; kf < 8; kf++) {
            uint32_t ah[4], al[4];
            uint32_t aoff = (w * 16 + a_row) * AROWB + kf * 32 + a_kh * 16;
            ldm_x4(ah, Qhi + aoff);
            ldm_x4(al, Qlo + aoff);
#pragma unroll
            for (int nt = 0; nt < 4; nt++) {
                uint32_t bh[4];
                uint32_t boff = (nt * 16 + b_nrow) * AROWB + kf * 32 + b_kh * 16;
                ldm_x4(bh, Kt + boff);
                mma16816h(S[2 * nt],     ah, bh[0], bh[1]);
                mma16816h(S[2 * nt + 1], ah, bh[2], bh[3]);
                mma16816h(S[2 * nt],     al, bh[0], bh[1]);
                mma16816h(S[2 * nt + 1], al, bh[2], bh[3]);
            }
        }

#pragma unroll
        for (int nf = 0; nf < 8; nf++) {
            int c0 = s0 + nf * 8 + qc2;
#pragma unroll
            for (int c = 0; c < 4; c++) {
                int col = c0 + (c & 1);
                int row = (c < 2) ? qrow0 : qrow1;
                bool ok = (col <= row) && (col > row - window);
                S[nf][c] = ok ? S[nf][c] * sc : -1e30f;
            }
        }

        float mx0 = -1e30f, mx1 = -1e30f;
#pragma unroll
        for (int nf = 0; nf < 8; nf++) {
            mx0 = fmaxf(mx0, fmaxf(S[nf][0], S[nf][1]));
            mx1 = fmaxf(mx1, fmaxf(S[nf][2], S[nf][3]));
        }
        mx0 = fmaxf(mx0, __shfl_xor_sync(0xffffffffu, mx0, 1));
        mx0 = fmaxf(mx0, __shfl_xor_sync(0xffffffffu, mx0, 2));
        mx1 = fmaxf(mx1, __shfl_xor_sync(0xffffffffu, mx1, 1));
        mx1 = fmaxf(mx1, __shfl_xor_sync(0xffffffffu, mx1, 2));

        float mn0 = fmaxf(m0, mx0), mn1 = fmaxf(m1, mx1);
        float corr0 = ex2(m0 - mn0), corr1 = ex2(m1 - mn1);
        m0 = mn0; m1 = mn1;

        uint32_t Phi[4][4], Plo[4][4];
        float rs0 = 0.0f, rs1 = 0.0f;
#pragma unroll
        for (int nf = 0; nf < 8; nf++) {
            float p0 = ex2(S[nf][0] - mn0);
            float p1 = ex2(S[nf][1] - mn0);
            float p2 = ex2(S[nf][2] - mn1);
            float p3 = ex2(S[nf][3] - mn1);
            rs0 += p0 + p1;
            rs1 += p2 + p3;
            __half h0 = __float2half(p0), h1 = __float2half(p1);
            __half h2 = __float2half(p2), h3 = __float2half(p3);
            __half e0 = __float2half(p0 - __half2float(h0));
            __half e1 = __float2half(p1 - __half2float(h1));
            __half e2 = __float2half(p2 - __half2float(h2));
            __half e3 = __float2half(p3 - __half2float(h3));
            const int kf = nf >> 1;
            if ((nf & 1) == 0) {
                Phi[kf][0] = pack2h(h0, h1); Phi[kf][1] = pack2h(h2, h3);
                Plo[kf][0] = pack2h(e0, e1); Plo[kf][1] = pack2h(e2, e3);
            } else {
                Phi[kf][2] = pack2h(h0, h1); Phi[kf][3] = pack2h(h2, h3);
                Plo[kf][2] = pack2h(e0, e1); Plo[kf][3] = pack2h(e2, e3);
            }
        }
        rs0 += __shfl_xor_sync(0xffffffffu, rs0, 1);
        rs0 += __shfl_xor_sync(0xffffffffu, rs0, 2);
        rs1 += __shfl_xor_sync(0xffffffffu, rs1, 1);
        rs1 += __shfl_xor_sync(0xffffffffu, rs1, 2);

        l0 = l0 * corr0 + rs0;
        l1 = l1 * corr1 + rs1;
#pragma unroll
        for (int nf = 0; nf < 16; nf++) {
            O[nf][0] *= corr0; O[nf][1] *= corr0;
            O[nf][2] *= corr1; O[nf][3] *= corr1;
        }

#pragma unroll
        for (int kf = 0; kf < 4; kf++) {
#pragma unroll
            for (int nt = 0; nt < 8; nt++) {
                uint32_t vh[4];
                uint32_t voff = (kf * 16 + vkr) * AROWB + (nt * 16 + vnc) * 2;
                ldm_x4_t(vh, Vt + voff);
                mma16816h(O[2 * nt],     Phi[kf], vh[0], vh[1]);
                mma16816h(O[2 * nt + 1], Phi[kf], vh[2], vh[3]);
                mma16816h(O[2 * nt],     Plo[kf], vh[0], vh[1]);
                mma16816h(O[2 * nt + 1], Plo[kf], vh[2], vh[3]);
            }
        }

        __syncthreads();
        if (it + 2 < nIter) load_kv(cur, s0 + 128);
    }

    const float inv0 = 1.0f / l0, inv1 = 1.0f / l1;
#pragma unroll
    for (int nf = 0; nf < 16; nf++) {
        int col = nf * 8 + qc2;
        size_t base0 = (size_t)qrow0 * HID + h * HD + col;
        size_t base1 = (size_t)qrow1 * HID + h * HD + col;
        float x0 = O[nf][0] * inv0, x1 = O[nf][1] * inv0;
        float x2 = O[nf][2] * inv1, x3 = O[nf][3] * inv1;
        __half h0 = __float2half(x0), h1 = __float2half(x1);
        __half h2 = __float2half(x2), h3 = __float2half(x3);
        *(uint32_t*)(outHi + base0) = pack2h(h0, h1);
        *(uint32_t*)(outHi + base1) = pack2h(h2, h3);
        __half e0 = __float2half(x0 - __half2float(h0));
        __half e1 = __float2half(x1 - __half2float(h1));
        __half e2 = __float2half(x2 - __half2float(h2));
        __half e3 = __float2half(x3 - __half2float(h3));
        *(uint32_t*)(outLo + base0) = pack2h(e0, e1);
        *(uint32_t*)(outLo + base1) = pack2h(e2, e3);
    }
}

// ---------------------------------------------------------------------------
extern "C" void kernel_launch(void* const* d_in, const int* in_sizes, int n_in,
                              void* d_out, int out_size)
{
    const int*   positions = (const int*)d_in[0];
    const float* hidden    = (const float*)d_in[1];
    const float* wqkv      = (const float*)d_in[2];
    const float* bqkv      = (const float*)d_in[3];
    const float* wo        = (const float*)d_in[4];
    const float* bo        = (const float*)d_in[5];
    const int*   window    = (const int*)d_in[6];
    float* out = (float*)d_out;

    float* qkv_ptr;
    __half *qkv_hi, *qkv_lo;
    __half *hid_hi, *hid_lo, *wqkv_h, *wo_h, *attn_hi, *attn_lo;
    cudaGetSymbolAddress((void**)&qkv_ptr,  g_qkv);
    cudaGetSymbolAddress((void**)&qkv_hi,   g_qkv_hi);
    cudaGetSymbolAddress((void**)&qkv_lo,   g_qkv_lo);
    cudaGetSymbolAddress((void**)&hid_hi,   g_hid_hi);
    cudaGetSymbolAddress((void**)&hid_lo,   g_hid_lo);
    cudaGetSymbolAddress((void**)&wqkv_h,   g_wqkv_h);
    cudaGetSymbolAddress((void**)&wo_h,     g_wo_h);
    cudaGetSymbolAddress((void**)&attn_hi,  g_attn_hi);
    cudaGetSymbolAddress((void**)&attn_lo,  g_attn_lo);

    cudaFuncSetAttribute(gemm_f16, cudaFuncAttributeMaxDynamicSharedMemorySize, GEMM_SMEM);
    cudaFuncSetAttribute(attn_mma, cudaFuncAttributeMaxDynamicSharedMemorySize, ATTN_SMEM);

    const int nHid  = TT * HID;
    const int nWqkv = QKVD * HID;
    const int nWo   = HID * HID;

    split_f16<<<(nHid / 4 + 255) / 256, 256>>>(hidden, hid_hi, hid_lo, nHid / 4);
    conv_f16<<<(nWqkv / 4 + 255) / 256, 256>>>(wqkv, wqkv_h, nWqkv / 4);

    gemm_f16<<<dim3(TT / GBM, QKVD / GBN), 256, GEMM_SMEM>>>(
        hid_hi, hid_lo, wqkv_h, bqkv, qkv_ptr, TT, QKVD, HID);

    rope_split<<<dim3(6, TT), 512>>>(qkv_ptr, positions, qkv_hi, qkv_lo);

    attn_mma<<<dim3(TT / 128, NH), 256, ATTN_SMEM>>>(qkv_hi, qkv_lo, attn_hi, attn_lo, window);

    conv_f16<<<(nWo / 4 + 255) / 256, 256>>>(wo, wo_h, nWo / 4);

    gemm_f16<<<dim3(TT / GBM, HID / GBN), 256, GEMM_SMEM>>>(
        attn_hi, attn_lo, wo_h, bo, out, TT, HID, HID);
}